// round 2
// baseline (speedup 1.0000x reference)
#include <cuda_runtime.h>

#define BATCH 32
#define SEQ   1024
#define DIM   256

// Scratch for Q, K, V projections (static device memory — no allocation).
__device__ float g_qkv[3][(size_t)BATCH * SEQ * DIM];

// ---------------------------------------------------------------------------
// Kernel 1: Y = X @ W^T + b for the three projection weights.
// X: [B*N, 256] row-major. W: [256, 256] row-major (out_feat, in_feat).
// Grid: (rows/128, cols/128, 3). 256 threads, 8x8 outputs per thread.
// ---------------------------------------------------------------------------
__global__ __launch_bounds__(256) void linear_qkv_kernel(
    const float* __restrict__ X,
    const float* __restrict__ Wq, const float* __restrict__ bq,
    const float* __restrict__ Wk, const float* __restrict__ bk,
    const float* __restrict__ Wv, const float* __restrict__ bv)
{
    const int z = blockIdx.z;
    const float* W    = (z == 0) ? Wq : ((z == 1) ? Wk : Wv);
    const float* bias = (z == 0) ? bq : ((z == 1) ? bk : bv);
    float* Y = g_qkv[z];

    __shared__ float As[16][132];  // As[k][row]
    __shared__ float Bs[16][132];  // Bs[k][col] = W[col][k]

    const int tid = threadIdx.x;
    const int tx = tid & 15, ty = tid >> 4;
    const int rbase = blockIdx.x * 128;
    const int cbase = blockIdx.y * 128;

    float acc[8][8];
#pragma unroll
    for (int i = 0; i < 8; i++)
#pragma unroll
        for (int j = 0; j < 8; j++) acc[i][j] = 0.f;

    for (int kc = 0; kc < 16; kc++) {
#pragma unroll
        for (int t = 0; t < 2; t++) {
            int task = tid + 256 * t;
            int r  = task & 127;
            int qd = task >> 7;  // 0..3
            float4 va = *(const float4*)&X[(size_t)(rbase + r) * DIM + kc * 16 + qd * 4];
            As[qd * 4 + 0][r] = va.x; As[qd * 4 + 1][r] = va.y;
            As[qd * 4 + 2][r] = va.z; As[qd * 4 + 3][r] = va.w;
            float4 vb = *(const float4*)&W[(size_t)(cbase + r) * DIM + kc * 16 + qd * 4];
            Bs[qd * 4 + 0][r] = vb.x; Bs[qd * 4 + 1][r] = vb.y;
            Bs[qd * 4 + 2][r] = vb.z; Bs[qd * 4 + 3][r] = vb.w;
        }
        __syncthreads();
#pragma unroll
        for (int k = 0; k < 16; k++) {
            float a[8], bb[8];
#pragma unroll
            for (int i = 0; i < 8; i++) a[i] = As[k][ty + 16 * i];
#pragma unroll
            for (int g = 0; g < 2; g++) {
                float4 v4 = *(const float4*)&Bs[k][g * 64 + tx * 4];
                bb[g * 4 + 0] = v4.x; bb[g * 4 + 1] = v4.y;
                bb[g * 4 + 2] = v4.z; bb[g * 4 + 3] = v4.w;
            }
#pragma unroll
            for (int i = 0; i < 8; i++)
#pragma unroll
                for (int j = 0; j < 8; j++)
                    acc[i][j] = fmaf(a[i], bb[j], acc[i][j]);
        }
        __syncthreads();
    }

#pragma unroll
    for (int i = 0; i < 8; i++) {
        int r = rbase + ty + 16 * i;
#pragma unroll
        for (int g = 0; g < 2; g++) {
            int c = cbase + g * 64 + tx * 4;
            float4 o4;
            o4.x = acc[i][g * 4 + 0] + bias[c + 0];
            o4.y = acc[i][g * 4 + 1] + bias[c + 1];
            o4.z = acc[i][g * 4 + 2] + bias[c + 2];
            o4.w = acc[i][g * 4 + 3] + bias[c + 3];
            *(float4*)&Y[(size_t)r * DIM + c] = o4;
        }
    }
}

// ---------------------------------------------------------------------------
// Kernel 2: flash attention (unscaled scores, softmax over full N=1024).
// Grid: (N/64, B). 256 threads. Q tile 64 rows fully resident in smem,
// K tiles of 128 rows streamed; online softmax; O in 64 regs/thread.
// ---------------------------------------------------------------------------
__global__ __launch_bounds__(256) void attn_kernel(float* __restrict__ out)
{
    extern __shared__ float sm[];
    float* Qs      = sm;                 // [256][64]   (Qs[d][row])
    float* Ps      = Qs + 256 * 64;      // [64][132]
    float* KVs     = Ps + 64 * 132;      // 8192 floats (K: [32][128], V: [32][256])
    float* rowmax  = KVs + 8192;         // [64]
    float* rowsum  = rowmax + 64;        // [64]
    float* rowcorr = rowsum + 64;        // [64]

    const float* qg = g_qkv[0];
    const float* kg = g_qkv[1];
    const float* vg = g_qkv[2];

    const int b     = blockIdx.y;
    const int qbase = blockIdx.x * 64;
    const int tid = threadIdx.x;
    const int tx = tid & 15, ty = tid >> 4;

    // Load Q tile transposed: Qs[d][r]
    const float4* q4 = (const float4*)(qg + (size_t)(b * SEQ + qbase) * DIM);
#pragma unroll
    for (int t = 0; t < 16; t++) {
        int task = tid + 256 * t;
        int r  = task & 63;
        int qd = task >> 6;  // 0..63
        float4 v = q4[r * 64 + qd];
        Qs[(qd * 4 + 0) * 64 + r] = v.x;
        Qs[(qd * 4 + 1) * 64 + r] = v.y;
        Qs[(qd * 4 + 2) * 64 + r] = v.z;
        Qs[(qd * 4 + 3) * 64 + r] = v.w;
    }
    if (tid < 64) { rowmax[tid] = -1e30f; rowsum[tid] = 0.f; }

    float o[4][16];
#pragma unroll
    for (int i = 0; i < 4; i++)
#pragma unroll
        for (int j = 0; j < 16; j++) o[i][j] = 0.f;
    __syncthreads();

    for (int mt = 0; mt < 8; mt++) {
        const int mbase = mt * 128;
        float s[4][8];
#pragma unroll
        for (int i = 0; i < 4; i++)
#pragma unroll
            for (int j = 0; j < 8; j++) s[i][j] = 0.f;

        // ---- S = Q K^T over d-chunks of 32 ----
        const float4* k4 = (const float4*)(kg + (size_t)(b * SEQ + mbase) * DIM);
        for (int dc = 0; dc < 8; dc++) {
#pragma unroll
            for (int t = 0; t < 4; t++) {
                int task = tid + 256 * t;
                int m  = task & 127;
                int qd = task >> 7;  // 0..7
                float4 v = k4[m * 64 + dc * 8 + qd];
                KVs[(qd * 4 + 0) * 128 + m] = v.x;
                KVs[(qd * 4 + 1) * 128 + m] = v.y;
                KVs[(qd * 4 + 2) * 128 + m] = v.z;
                KVs[(qd * 4 + 3) * 128 + m] = v.w;
            }
            __syncthreads();
#pragma unroll 4
            for (int kd = 0; kd < 32; kd++) {
                float qr[4], kr[8];
#pragma unroll
                for (int i = 0; i < 4; i++)
                    qr[i] = Qs[(dc * 32 + kd) * 64 + ty + 16 * i];
#pragma unroll
                for (int g = 0; g < 2; g++) {
                    float4 kv = *(const float4*)&KVs[kd * 128 + g * 64 + tx * 4];
                    kr[g * 4 + 0] = kv.x; kr[g * 4 + 1] = kv.y;
                    kr[g * 4 + 2] = kv.z; kr[g * 4 + 3] = kv.w;
                }
#pragma unroll
                for (int i = 0; i < 4; i++)
#pragma unroll
                    for (int j = 0; j < 8; j++)
                        s[i][j] = fmaf(qr[i], kr[j], s[i][j]);
            }
            __syncthreads();
        }

        // ---- write S tile to smem ----
#pragma unroll
        for (int i = 0; i < 4; i++)
#pragma unroll
            for (int g = 0; g < 2; g++) {
                float4 sv;
                sv.x = s[i][g * 4 + 0]; sv.y = s[i][g * 4 + 1];
                sv.z = s[i][g * 4 + 2]; sv.w = s[i][g * 4 + 3];
                *(float4*)&Ps[(ty + 16 * i) * 132 + g * 64 + tx * 4] = sv;
            }
        __syncthreads();

        // ---- online softmax: 4 threads per row ----
        {
            int row = tid >> 2, part = tid & 3;
            float* prow = Ps + row * 132 + part * 32;
            float mloc = -1e30f;
#pragma unroll 8
            for (int c = 0; c < 32; c++) mloc = fmaxf(mloc, prow[c]);
            mloc = fmaxf(mloc, __shfl_xor_sync(0xffffffffu, mloc, 1));
            mloc = fmaxf(mloc, __shfl_xor_sync(0xffffffffu, mloc, 2));
            float mold = rowmax[row];
            float mnew = fmaxf(mold, mloc);
            float corr = __expf(mold - mnew);
            float ssum = 0.f;
#pragma unroll 8
            for (int c = 0; c < 32; c++) {
                float p = __expf(prow[c] - mnew);
                prow[c] = p;
                ssum += p;
            }
            ssum += __shfl_xor_sync(0xffffffffu, ssum, 1);
            ssum += __shfl_xor_sync(0xffffffffu, ssum, 2);
            if (part == 0) {
                rowmax[row]  = mnew;
                rowsum[row]  = rowsum[row] * corr + ssum;
                rowcorr[row] = corr;
            }
        }
        __syncthreads();

        // ---- rescale O by correction factors ----
#pragma unroll
        for (int i = 0; i < 4; i++) {
            float ci = rowcorr[ty + 16 * i];
#pragma unroll
            for (int j = 0; j < 16; j++) o[i][j] *= ci;
        }

        // ---- O += P @ V over m-chunks of 32 ----
        const float4* v4 = (const float4*)(vg + (size_t)(b * SEQ + mbase) * DIM);
        for (int mc = 0; mc < 4; mc++) {
            __syncthreads();
#pragma unroll
            for (int t = 0; t < 8; t++) {
                int task = tid + 256 * t;
                int qd = task & 63;
                int vm = task >> 6;  // 0..31
                float4 v = v4[(mc * 32 + vm) * 64 + qd];
                *(float4*)&KVs[vm * 256 + qd * 4] = v;
            }
            __syncthreads();
#pragma unroll 4
            for (int km = 0; km < 32; km++) {
                float pr[4], vr[16];
#pragma unroll
                for (int i = 0; i < 4; i++)
                    pr[i] = Ps[(ty + 16 * i) * 132 + mc * 32 + km];
#pragma unroll
                for (int g = 0; g < 4; g++) {
                    float4 vv = *(const float4*)&KVs[km * 256 + g * 64 + tx * 4];
                    vr[g * 4 + 0] = vv.x; vr[g * 4 + 1] = vv.y;
                    vr[g * 4 + 2] = vv.z; vr[g * 4 + 3] = vv.w;
                }
#pragma unroll
                for (int i = 0; i < 4; i++)
#pragma unroll
                    for (int j = 0; j < 16; j++)
                        o[i][j] = fmaf(pr[i], vr[j], o[i][j]);
            }
        }
        __syncthreads();
    }

    // ---- epilogue: O /= rowsum, write out ----
#pragma unroll
    for (int i = 0; i < 4; i++) {
        float inv = 1.0f / rowsum[ty + 16 * i];
        int r = b * SEQ + qbase + ty + 16 * i;
#pragma unroll
        for (int g = 0; g < 4; g++) {
            float4 o4;
            o4.x = o[i][g * 4 + 0] * inv;
            o4.y = o[i][g * 4 + 1] * inv;
            o4.z = o[i][g * 4 + 2] * inv;
            o4.w = o[i][g * 4 + 3] * inv;
            *(float4*)&out[(size_t)r * DIM + g * 64 + tx * 4] = o4;
        }
    }
}

// ---------------------------------------------------------------------------
extern "C" void kernel_launch(void* const* d_in, const int* in_sizes, int n_in,
                              void* d_out, int out_size)
{
    const float* traj = (const float*)d_in[0];
    const float* Wq   = (const float*)d_in[1];
    const float* bq   = (const float*)d_in[2];
    const float* Wk   = (const float*)d_in[3];
    const float* bk   = (const float*)d_in[4];
    const float* Wv   = (const float*)d_in[5];
    const float* bv   = (const float*)d_in[6];
    float* out = (float*)d_out;

    // QKV projections: rows = 32768 / 128 = 256 tiles, cols = 256/128 = 2 tiles, z = 3 weights
    linear_qkv_kernel<<<dim3(256, 2, 3), 256>>>(traj, Wq, bq, Wk, bk, Wv, bv);

    // Flash attention
    const size_t smem_bytes = (size_t)(256 * 64 + 64 * 132 + 8192 + 192) * sizeof(float);
    cudaFuncSetAttribute(attn_kernel, cudaFuncAttributeMaxDynamicSharedMemorySize,
                         (int)smem_bytes);
    attn_kernel<<<dim3(SEQ / 64, BATCH), 256, smem_bytes>>>(out);
}

// round 4
// speedup vs baseline: 1.0039x; 1.0039x over previous
#include <cuda_runtime.h>

#define BATCH 32
#define SEQ   1024
#define DIM   256

// Scratch for Q, K, V projections (static device memory — no allocation).
__device__ float g_qkv[3][(size_t)BATCH * SEQ * DIM];

// ---------------------------------------------------------------------------
// Kernel 1: Y = X @ W^T + b for the three projection weights.
// X: [B*N, 256] row-major. W: [256, 256] row-major (out_feat, in_feat).
// Grid: (rows/128, cols/128, 3). 256 threads, 8x8 outputs per thread.
// ---------------------------------------------------------------------------
__global__ __launch_bounds__(256) void linear_qkv_kernel(
    const float* __restrict__ X,
    const float* __restrict__ Wq, const float* __restrict__ bq,
    const float* __restrict__ Wk, const float* __restrict__ bk,
    const float* __restrict__ Wv, const float* __restrict__ bv)
{
    const int z = blockIdx.z;
    const float* W    = (z == 0) ? Wq : ((z == 1) ? Wk : Wv);
    const float* bias = (z == 0) ? bq : ((z == 1) ? bk : bv);
    float* Y = g_qkv[z];

    __shared__ float As[16][132];  // As[k][row]
    __shared__ float Bs[16][132];  // Bs[k][col] = W[col][k]

    const int tid = threadIdx.x;
    const int tx = tid & 15, ty = tid >> 4;
    const int rbase = blockIdx.x * 128;
    const int cbase = blockIdx.y * 128;

    float acc[8][8];
#pragma unroll
    for (int i = 0; i < 8; i++)
#pragma unroll
        for (int j = 0; j < 8; j++) acc[i][j] = 0.f;

    for (int kc = 0; kc < 16; kc++) {
#pragma unroll
        for (int t = 0; t < 2; t++) {
            int task = tid + 256 * t;
            int r  = task & 127;
            int qd = task >> 7;  // 0..3
            float4 va = *(const float4*)&X[(size_t)(rbase + r) * DIM + kc * 16 + qd * 4];
            As[qd * 4 + 0][r] = va.x; As[qd * 4 + 1][r] = va.y;
            As[qd * 4 + 2][r] = va.z; As[qd * 4 + 3][r] = va.w;
            float4 vb = *(const float4*)&W[(size_t)(cbase + r) * DIM + kc * 16 + qd * 4];
            Bs[qd * 4 + 0][r] = vb.x; Bs[qd * 4 + 1][r] = vb.y;
            Bs[qd * 4 + 2][r] = vb.z; Bs[qd * 4 + 3][r] = vb.w;
        }
        __syncthreads();
#pragma unroll
        for (int k = 0; k < 16; k++) {
            float a[8], bb[8];
#pragma unroll
            for (int i = 0; i < 8; i++) a[i] = As[k][ty + 16 * i];
#pragma unroll
            for (int g = 0; g < 2; g++) {
                float4 v4 = *(const float4*)&Bs[k][g * 64 + tx * 4];
                bb[g * 4 + 0] = v4.x; bb[g * 4 + 1] = v4.y;
                bb[g * 4 + 2] = v4.z; bb[g * 4 + 3] = v4.w;
            }
#pragma unroll
            for (int i = 0; i < 8; i++)
#pragma unroll
                for (int j = 0; j < 8; j++)
                    acc[i][j] = fmaf(a[i], bb[j], acc[i][j]);
        }
        __syncthreads();
    }

#pragma unroll
    for (int i = 0; i < 8; i++) {
        int r = rbase + ty + 16 * i;
#pragma unroll
        for (int g = 0; g < 2; g++) {
            int c = cbase + g * 64 + tx * 4;
            float4 o4;
            o4.x = acc[i][g * 4 + 0] + bias[c + 0];
            o4.y = acc[i][g * 4 + 1] + bias[c + 1];
            o4.z = acc[i][g * 4 + 2] + bias[c + 2];
            o4.w = acc[i][g * 4 + 3] + bias[c + 3];
            *(float4*)&Y[(size_t)r * DIM + c] = o4;
        }
    }
}

// ---------------------------------------------------------------------------
// Kernel 2: flash attention (unscaled scores, softmax over full N=1024).
// Grid: (N/64, B). 256 threads. Q tile 64 rows fully resident in smem,
// K tiles of 128 rows streamed; online softmax; O in 64 regs/thread.
// ---------------------------------------------------------------------------
__global__ __launch_bounds__(256) void attn_kernel(float* __restrict__ out)
{
    extern __shared__ float sm[];
    float* Qs      = sm;                 // [256][64]   (Qs[d][row])
    float* Ps      = Qs + 256 * 64;      // [64][132]
    float* KVs     = Ps + 64 * 132;      // 8192 floats (K: [32][128], V: [32][256])
    float* rowmax  = KVs + 8192;         // [64]
    float* rowsum  = rowmax + 64;        // [64]
    float* rowcorr = rowsum + 64;        // [64]

    const float* qg = g_qkv[0];
    const float* kg = g_qkv[1];
    const float* vg = g_qkv[2];

    const int b     = blockIdx.y;
    const int qbase = blockIdx.x * 64;
    const int tid = threadIdx.x;
    const int tx = tid & 15, ty = tid >> 4;

    // Load Q tile transposed: Qs[d][r]
    const float4* q4 = (const float4*)(qg + (size_t)(b * SEQ + qbase) * DIM);
#pragma unroll
    for (int t = 0; t < 16; t++) {
        int task = tid + 256 * t;
        int r  = task & 63;
        int qd = task >> 6;  // 0..63
        float4 v = q4[r * 64 + qd];
        Qs[(qd * 4 + 0) * 64 + r] = v.x;
        Qs[(qd * 4 + 1) * 64 + r] = v.y;
        Qs[(qd * 4 + 2) * 64 + r] = v.z;
        Qs[(qd * 4 + 3) * 64 + r] = v.w;
    }
    if (tid < 64) { rowmax[tid] = -1e30f; rowsum[tid] = 0.f; }

    float o[4][16];
#pragma unroll
    for (int i = 0; i < 4; i++)
#pragma unroll
        for (int j = 0; j < 16; j++) o[i][j] = 0.f;
    __syncthreads();

    for (int mt = 0; mt < 8; mt++) {
        const int mbase = mt * 128;
        float s[4][8];
#pragma unroll
        for (int i = 0; i < 4; i++)
#pragma unroll
            for (int j = 0; j < 8; j++) s[i][j] = 0.f;

        // ---- S = Q K^T over d-chunks of 32 ----
        const float4* k4 = (const float4*)(kg + (size_t)(b * SEQ + mbase) * DIM);
        for (int dc = 0; dc < 8; dc++) {
#pragma unroll
            for (int t = 0; t < 4; t++) {
                int task = tid + 256 * t;
                int m  = task & 127;
                int qd = task >> 7;  // 0..7
                float4 v = k4[m * 64 + dc * 8 + qd];
                KVs[(qd * 4 + 0) * 128 + m] = v.x;
                KVs[(qd * 4 + 1) * 128 + m] = v.y;
                KVs[(qd * 4 + 2) * 128 + m] = v.z;
                KVs[(qd * 4 + 3) * 128 + m] = v.w;
            }
            __syncthreads();
#pragma unroll 4
            for (int kd = 0; kd < 32; kd++) {
                float qr[4], kr[8];
#pragma unroll
                for (int i = 0; i < 4; i++)
                    qr[i] = Qs[(dc * 32 + kd) * 64 + ty + 16 * i];
#pragma unroll
                for (int g = 0; g < 2; g++) {
                    float4 kv = *(const float4*)&KVs[kd * 128 + g * 64 + tx * 4];
                    kr[g * 4 + 0] = kv.x; kr[g * 4 + 1] = kv.y;
                    kr[g * 4 + 2] = kv.z; kr[g * 4 + 3] = kv.w;
                }
#pragma unroll
                for (int i = 0; i < 4; i++)
#pragma unroll
                    for (int j = 0; j < 8; j++)
                        s[i][j] = fmaf(qr[i], kr[j], s[i][j]);
            }
            __syncthreads();
        }

        // ---- write S tile to smem ----
#pragma unroll
        for (int i = 0; i < 4; i++)
#pragma unroll
            for (int g = 0; g < 2; g++) {
                float4 sv;
                sv.x = s[i][g * 4 + 0]; sv.y = s[i][g * 4 + 1];
                sv.z = s[i][g * 4 + 2]; sv.w = s[i][g * 4 + 3];
                *(float4*)&Ps[(ty + 16 * i) * 132 + g * 64 + tx * 4] = sv;
            }
        __syncthreads();

        // ---- online softmax: 4 threads per row ----
        {
            int row = tid >> 2, part = tid & 3;
            float* prow = Ps + row * 132 + part * 32;
            float mloc = -1e30f;
#pragma unroll 8
            for (int c = 0; c < 32; c++) mloc = fmaxf(mloc, prow[c]);
            mloc = fmaxf(mloc, __shfl_xor_sync(0xffffffffu, mloc, 1));
            mloc = fmaxf(mloc, __shfl_xor_sync(0xffffffffu, mloc, 2));
            float mold = rowmax[row];
            float mnew = fmaxf(mold, mloc);
            float corr = __expf(mold - mnew);
            float ssum = 0.f;
#pragma unroll 8
            for (int c = 0; c < 32; c++) {
                float p = __expf(prow[c] - mnew);
                prow[c] = p;
                ssum += p;
            }
            ssum += __shfl_xor_sync(0xffffffffu, ssum, 1);
            ssum += __shfl_xor_sync(0xffffffffu, ssum, 2);
            if (part == 0) {
                rowmax[row]  = mnew;
                rowsum[row]  = rowsum[row] * corr + ssum;
                rowcorr[row] = corr;
            }
        }
        __syncthreads();

        // ---- rescale O by correction factors ----
#pragma unroll
        for (int i = 0; i < 4; i++) {
            float ci = rowcorr[ty + 16 * i];
#pragma unroll
            for (int j = 0; j < 16; j++) o[i][j] *= ci;
        }

        // ---- O += P @ V over m-chunks of 32 ----
        const float4* v4 = (const float4*)(vg + (size_t)(b * SEQ + mbase) * DIM);
        for (int mc = 0; mc < 4; mc++) {
            __syncthreads();
#pragma unroll
            for (int t = 0; t < 8; t++) {
                int task = tid + 256 * t;
                int qd = task & 63;
                int vm = task >> 6;  // 0..31
                float4 v = v4[(mc * 32 + vm) * 64 + qd];
                *(float4*)&KVs[vm * 256 + qd * 4] = v;
            }
            __syncthreads();
#pragma unroll 4
            for (int km = 0; km < 32; km++) {
                float pr[4], vr[16];
#pragma unroll
                for (int i = 0; i < 4; i++)
                    pr[i] = Ps[(ty + 16 * i) * 132 + mc * 32 + km];
#pragma unroll
                for (int g = 0; g < 4; g++) {
                    float4 vv = *(const float4*)&KVs[km * 256 + g * 64 + tx * 4];
                    vr[g * 4 + 0] = vv.x; vr[g * 4 + 1] = vv.y;
                    vr[g * 4 + 2] = vv.z; vr[g * 4 + 3] = vv.w;
                }
#pragma unroll
                for (int i = 0; i < 4; i++)
#pragma unroll
                    for (int j = 0; j < 16; j++)
                        o[i][j] = fmaf(pr[i], vr[j], o[i][j]);
            }
        }
        __syncthreads();
    }

    // ---- epilogue: O /= rowsum, write out ----
#pragma unroll
    for (int i = 0; i < 4; i++) {
        float inv = 1.0f / rowsum[ty + 16 * i];
        int r = b * SEQ + qbase + ty + 16 * i;
#pragma unroll
        for (int g = 0; g < 4; g++) {
            float4 o4;
            o4.x = o[i][g * 4 + 0] * inv;
            o4.y = o[i][g * 4 + 1] * inv;
            o4.z = o[i][g * 4 + 2] * inv;
            o4.w = o[i][g * 4 + 3] * inv;
            *(float4*)&out[(size_t)r * DIM + g * 64 + tx * 4] = o4;
        }
    }
}

// ---------------------------------------------------------------------------
extern "C" void kernel_launch(void* const* d_in, const int* in_sizes, int n_in,
                              void* d_out, int out_size)
{
    const float* traj = (const float*)d_in[0];
    const float* Wq   = (const float*)d_in[1];
    const float* bq   = (const float*)d_in[2];
    const float* Wk   = (const float*)d_in[3];
    const float* bk   = (const float*)d_in[4];
    const float* Wv   = (const float*)d_in[5];
    const float* bv   = (const float*)d_in[6];
    float* out = (float*)d_out;

    // QKV projections: rows = 32768 / 128 = 256 tiles, cols = 256/128 = 2 tiles, z = 3 weights
    linear_qkv_kernel<<<dim3(256, 2, 3), 256>>>(traj, Wq, bq, Wk, bk, Wv, bv);

    // Flash attention
    const size_t smem_bytes = (size_t)(256 * 64 + 64 * 132 + 8192 + 192) * sizeof(float);
    cudaFuncSetAttribute(attn_kernel, cudaFuncAttributeMaxDynamicSharedMemorySize,
                         (int)smem_bytes);
    attn_kernel<<<dim3(SEQ / 64, BATCH), 256, smem_bytes>>>(out);
}

// round 7
// speedup vs baseline: 2.4659x; 2.4563x over previous
#include <cuda_runtime.h>
#include <cuda_fp16.h>
#include <cstdint>

#define BATCH 32
#define SEQ   1024
#define DIM   256
#define NROWS (BATCH * SEQ)

// static scratch: fp16 hi/lo pairs
__device__ __align__(256) __half g_q [2][(size_t)NROWS * DIM];  // [b*N+n][d]
__device__ __align__(256) __half g_k [2][(size_t)NROWS * DIM];  // [b*N+m][d]
__device__ __align__(256) __half g_v [2][(size_t)NROWS * DIM];  // [b*N+m][d]
__device__ __align__(256) __half g_vt[2][(size_t)NROWS * DIM];  // [(b*256+d)*1024+m]

// ---------------- mma.sync + fragment helpers ----------------
__device__ __forceinline__ void mma16816(float* d, const uint32_t* a, const uint32_t* b) {
    asm volatile("mma.sync.aligned.m16n8k16.row.col.f32.f16.f16.f32 "
        "{%0,%1,%2,%3}, {%4,%5,%6,%7}, {%8,%9}, {%0,%1,%2,%3};"
        : "+f"(d[0]), "+f"(d[1]), "+f"(d[2]), "+f"(d[3])
        : "r"(a[0]), "r"(a[1]), "r"(a[2]), "r"(a[3]), "r"(b[0]), "r"(b[1]));
}
// A frag (m16 x k16) from row-major fp16 smem (k contiguous), stride S halfs
__device__ __forceinline__ void lda(uint32_t* a, const __half* base, int S, int lane) {
    int r = lane >> 2, q = (lane & 3) * 2;
    a[0] = *(const uint32_t*)(base + r * S + q);
    a[1] = *(const uint32_t*)(base + (r + 8) * S + q);
    a[2] = *(const uint32_t*)(base + r * S + q + 8);
    a[3] = *(const uint32_t*)(base + (r + 8) * S + q + 8);
}
// B frag (k16 x n8) from [n][k] fp16 smem (k contiguous), stride S halfs
__device__ __forceinline__ void ldb(uint32_t* b, const __half* base, int S, int lane) {
    int r = lane >> 2, q = (lane & 3) * 2;
    b[0] = *(const uint32_t*)(base + r * S + q);
    b[1] = *(const uint32_t*)(base + r * S + q + 8);
}
__device__ __forceinline__ void splitf(float x, __half& h, __half& l) {
    h = __float2half_rn(x);
    l = __float2half_rn(x - __half2float(h));
}
__device__ __forceinline__ uint32_t packh(__half a, __half b) {
    __half2 h2 = __halves2half2(a, b);
    return *reinterpret_cast<uint32_t*>(&h2);
}

// ---------------- projection: Y = X @ W^T + b (fp16-split 3-MMA) ----------------
// grid (256 row-tiles, 2 col-tiles, 3 weights), 256 threads (8 warps, warp 32x64)
#define PJ_S 72
#define PJ_SMEM (4 * 18432)
__global__ __launch_bounds__(256, 1) void proj_kernel(
    const float* __restrict__ X,
    const float* __restrict__ Wq, const float* __restrict__ Wk, const float* __restrict__ Wv,
    const float* __restrict__ bq, const float* __restrict__ bk, const float* __restrict__ bv)
{
    extern __shared__ char sm[];
    __half* AH = (__half*)(sm);
    __half* AL = (__half*)(sm + 18432);
    __half* BH = (__half*)(sm + 36864);
    __half* BL = (__half*)(sm + 55296);

    const int tid = threadIdx.x, lane = tid & 31, w = tid >> 5;
    const int wy = w >> 1, wx = w & 1;
    const int rbase = blockIdx.x * 128, cbase = blockIdx.y * 128, z = blockIdx.z;
    const float* W    = (z == 0) ? Wq : ((z == 1) ? Wk : Wv);
    const float* bias = (z == 0) ? bq : ((z == 1) ? bk : bv);

    float acc[2][8][4];
#pragma unroll
    for (int mi = 0; mi < 2; mi++)
#pragma unroll
        for (int nj = 0; nj < 8; nj++)
#pragma unroll
            for (int c = 0; c < 4; c++) acc[mi][nj][c] = 0.f;

    for (int kc = 0; kc < 4; kc++) {
        __syncthreads();
#pragma unroll
        for (int it = 0; it < 8; it++) {
            int task = tid + 256 * it;
            int r = task >> 4, c4 = (task & 15) * 4;
            float4 xv = *(const float4*)&X[(size_t)(rbase + r) * DIM + kc * 64 + c4];
            __half h0, l0, h1, l1, h2, l2, h3, l3;
            splitf(xv.x, h0, l0); splitf(xv.y, h1, l1);
            splitf(xv.z, h2, l2); splitf(xv.w, h3, l3);
            *(uint32_t*)&AH[r * PJ_S + c4]     = packh(h0, h1);
            *(uint32_t*)&AH[r * PJ_S + c4 + 2] = packh(h2, h3);
            *(uint32_t*)&AL[r * PJ_S + c4]     = packh(l0, l1);
            *(uint32_t*)&AL[r * PJ_S + c4 + 2] = packh(l2, l3);
            float4 wv = *(const float4*)&W[(size_t)(cbase + r) * DIM + kc * 64 + c4];
            splitf(wv.x, h0, l0); splitf(wv.y, h1, l1);
            splitf(wv.z, h2, l2); splitf(wv.w, h3, l3);
            *(uint32_t*)&BH[r * PJ_S + c4]     = packh(h0, h1);
            *(uint32_t*)&BH[r * PJ_S + c4 + 2] = packh(h2, h3);
            *(uint32_t*)&BL[r * PJ_S + c4]     = packh(l0, l1);
            *(uint32_t*)&BL[r * PJ_S + c4 + 2] = packh(l2, l3);
        }
        __syncthreads();
#pragma unroll
        for (int ks = 0; ks < 4; ks++) {
            uint32_t ah[2][4], al[2][4];
#pragma unroll
            for (int mi = 0; mi < 2; mi++) {
                lda(ah[mi], AH + (wy * 32 + mi * 16) * PJ_S + ks * 16, PJ_S, lane);
                lda(al[mi], AL + (wy * 32 + mi * 16) * PJ_S + ks * 16, PJ_S, lane);
            }
#pragma unroll
            for (int nj = 0; nj < 8; nj++) {
                uint32_t bh[2], bl[2];
                ldb(bh, BH + (wx * 64 + nj * 8) * PJ_S + ks * 16, PJ_S, lane);
                ldb(bl, BL + (wx * 64 + nj * 8) * PJ_S + ks * 16, PJ_S, lane);
#pragma unroll
                for (int mi = 0; mi < 2; mi++) {
                    mma16816(acc[mi][nj], ah[mi], bh);
                    mma16816(acc[mi][nj], ah[mi], bl);
                    mma16816(acc[mi][nj], al[mi], bh);
                }
            }
        }
    }

    uint32_t* dh = (uint32_t*)((z == 0) ? g_q[0] : (z == 1) ? g_k[0] : g_v[0]);
    uint32_t* dl = (uint32_t*)((z == 0) ? g_q[1] : (z == 1) ? g_k[1] : g_v[1]);
#pragma unroll
    for (int mi = 0; mi < 2; mi++) {
        int rA = rbase + wy * 32 + mi * 16 + (lane >> 2);
#pragma unroll
        for (int nj = 0; nj < 8; nj++) {
            int col = cbase + wx * 64 + nj * 8 + 2 * (lane & 3);
            float b0 = __ldg(&bias[col]), b1 = __ldg(&bias[col + 1]);
            __half h0, l0, h1, l1;
            float y0 = acc[mi][nj][0] + b0, y1 = acc[mi][nj][1] + b1;
            splitf(y0, h0, l0); splitf(y1, h1, l1);
            dh[(size_t)rA * 128 + (col >> 1)] = packh(h0, h1);
            dl[(size_t)rA * 128 + (col >> 1)] = packh(l0, l1);
            float y2 = acc[mi][nj][2] + b0, y3 = acc[mi][nj][3] + b1;
            splitf(y2, h0, l0); splitf(y3, h1, l1);
            dh[(size_t)(rA + 8) * 128 + (col >> 1)] = packh(h0, h1);
            dl[(size_t)(rA + 8) * 128 + (col >> 1)] = packh(l0, l1);
        }
    }
}

// ---------------- V transpose: g_v[(b*N+m)*256+d] -> g_vt[(b*256+d)*1024+m] ----
__global__ __launch_bounds__(256) void vt_kernel()
{
    __shared__ __half t0[32][33], t1[32][33];
    const int b = blockIdx.z, d0 = blockIdx.y * 32, m0 = blockIdx.x * 32;
    const int tx = threadIdx.x, ty = threadIdx.y;
#pragma unroll
    for (int i = 0; i < 4; i++) {
        int m = ty + 8 * i;
        size_t src = ((size_t)b * SEQ + m0 + m) * DIM + d0 + tx;
        t0[m][tx] = g_v[0][src];
        t1[m][tx] = g_v[1][src];
    }
    __syncthreads();
#pragma unroll
    for (int i = 0; i < 4; i++) {
        int d = ty + 8 * i;
        size_t dst = ((size_t)b * DIM + d0 + d) * SEQ + m0 + tx;
        g_vt[0][dst] = t0[tx][d];
        g_vt[1][dst] = t1[tx][d];
    }
}

// ---------------- attention: mma.sync flash, 64 q-rows/CTA, 8 warps ----------------
#define AT_QS 264
#define AT_KS 72
#define AT_PS 136
#define A_QH 0
#define A_QL 33792
#define A_KH 67584
#define A_KL 86016
#define A_PH 104448
#define A_PL 121856
#define A_ST 139264
#define AT_SMEM 141056
__global__ __launch_bounds__(256, 1) void attn_kernel(float* __restrict__ out)
{
    extern __shared__ char sm[];
    __half* QH = (__half*)(sm + A_QH);
    __half* QL = (__half*)(sm + A_QL);
    __half* KH = (__half*)(sm + A_KH);   // also V^T chunk buffer
    __half* KL = (__half*)(sm + A_KL);
    __half* PH = (__half*)(sm + A_PH);
    __half* PL = (__half*)(sm + A_PL);
    float* rowmax  = (float*)(sm + A_ST);   // [64]
    float* rowsum  = rowmax + 64;           // [64]
    float* corr    = rowsum + 64;           // [64]
    float* halfmax = corr + 64;             // [64][2]
    float* halfsum = halfmax + 128;         // [64][2]

    const int b = blockIdx.y, qbase = blockIdx.x * 64;
    const int tid = threadIdx.x, lane = tid & 31, w = tid >> 5;
    const int qb = (w >> 1) * 16, mh = w & 1;
    const int r0 = qb + (lane >> 2), r1 = r0 + 8;

    // load Q tile (hi/lo) 64x256
    const uint4* qh4 = (const uint4*)(g_q[0] + (size_t)(b * SEQ + qbase) * DIM);
    const uint4* ql4 = (const uint4*)(g_q[1] + (size_t)(b * SEQ + qbase) * DIM);
#pragma unroll
    for (int it = 0; it < 16; it++) {
        int task = tid + 256 * it;
        int arr = task >> 11, idx = task & 2047;
        int r = idx >> 5, c8 = idx & 31;
        uint4 v = (arr ? ql4 : qh4)[r * 32 + c8];
        *(uint4*)&((arr ? QL : QH)[r * AT_QS + c8 * 8]) = v;
    }
    if (tid < 64) { rowmax[tid] = -1e30f; rowsum[tid] = 0.f; }

    float o[4][4][4];
#pragma unroll
    for (int dc = 0; dc < 4; dc++)
#pragma unroll
        for (int nj = 0; nj < 4; nj++)
#pragma unroll
            for (int c = 0; c < 4; c++) o[dc][nj][c] = 0.f;

    const uint4* kh4 = (const uint4*)(g_k[0] + (size_t)b * SEQ * DIM);
    const uint4* kl4 = (const uint4*)(g_k[1] + (size_t)b * SEQ * DIM);
    const uint4* vh4 = (const uint4*)(g_vt[0] + (size_t)b * DIM * SEQ);
    const uint4* vl4 = (const uint4*)(g_vt[1] + (size_t)b * DIM * SEQ);

    for (int mt = 0; mt < 8; mt++) {
        const int mbase = mt * 128;
        float s[8][4];
#pragma unroll
        for (int nj = 0; nj < 8; nj++)
#pragma unroll
            for (int c = 0; c < 4; c++) s[nj][c] = 0.f;

        // ---- S = Q K^T, d-chunks of 64 ----
        for (int dc = 0; dc < 4; dc++) {
            __syncthreads();
#pragma unroll
            for (int it = 0; it < 8; it++) {
                int task = tid + 256 * it;
                int arr = task >> 10, idx = task & 1023;
                int r = idx >> 3, c8 = idx & 7;
                uint4 v = (arr ? kl4 : kh4)[(mbase + r) * 32 + dc * 8 + c8];
                *(uint4*)&((arr ? KL : KH)[r * AT_KS + c8 * 8]) = v;
            }
            __syncthreads();
#pragma unroll
            for (int ks = 0; ks < 4; ks++) {
                uint32_t ah[4], al[4];
                lda(ah, QH + qb * AT_QS + dc * 64 + ks * 16, AT_QS, lane);
                lda(al, QL + qb * AT_QS + dc * 64 + ks * 16, AT_QS, lane);
#pragma unroll
                for (int nj = 0; nj < 8; nj++) {
                    uint32_t bh[2], bl[2];
                    ldb(bh, KH + (mh * 64 + nj * 8) * AT_KS + ks * 16, AT_KS, lane);
                    ldb(bl, KL + (mh * 64 + nj * 8) * AT_KS + ks * 16, AT_KS, lane);
                    mma16816(s[nj], ah, bh);
                    mma16816(s[nj], ah, bl);
                    mma16816(s[nj], al, bh);
                }
            }
        }

        // ---- online softmax ----
        float mx0 = -1e30f, mx1 = -1e30f;
#pragma unroll
        for (int nj = 0; nj < 8; nj++) {
            mx0 = fmaxf(mx0, fmaxf(s[nj][0], s[nj][1]));
            mx1 = fmaxf(mx1, fmaxf(s[nj][2], s[nj][3]));
        }
        mx0 = fmaxf(mx0, __shfl_xor_sync(0xffffffffu, mx0, 1));
        mx0 = fmaxf(mx0, __shfl_xor_sync(0xffffffffu, mx0, 2));
        mx1 = fmaxf(mx1, __shfl_xor_sync(0xffffffffu, mx1, 1));
        mx1 = fmaxf(mx1, __shfl_xor_sync(0xffffffffu, mx1, 2));
        if ((lane & 3) == 0) { halfmax[r0 * 2 + mh] = mx0; halfmax[r1 * 2 + mh] = mx1; }
        __syncthreads();
        if (tid < 64) {
            float mo = rowmax[tid];
            float mn = fmaxf(mo, fmaxf(halfmax[tid * 2], halfmax[tid * 2 + 1]));
            rowmax[tid] = mn;
            corr[tid] = __expf(mo - mn);
        }
        __syncthreads();
        float m0 = rowmax[r0], m1 = rowmax[r1];
        float sum0 = 0.f, sum1 = 0.f;
#pragma unroll
        for (int nj = 0; nj < 8; nj++) {
            int cc = mh * 64 + nj * 8 + 2 * (lane & 3);
            float e0 = __expf(s[nj][0] - m0), e1 = __expf(s[nj][1] - m0);
            float e2 = __expf(s[nj][2] - m1), e3 = __expf(s[nj][3] - m1);
            sum0 += e0 + e1; sum1 += e2 + e3;
            __half h0, l0, h1, l1;
            splitf(e0, h0, l0); splitf(e1, h1, l1);
            *(uint32_t*)&PH[r0 * AT_PS + cc] = packh(h0, h1);
            *(uint32_t*)&PL[r0 * AT_PS + cc] = packh(l0, l1);
            splitf(e2, h0, l0); splitf(e3, h1, l1);
            *(uint32_t*)&PH[r1 * AT_PS + cc] = packh(h0, h1);
            *(uint32_t*)&PL[r1 * AT_PS + cc] = packh(l0, l1);
        }
        sum0 += __shfl_xor_sync(0xffffffffu, sum0, 1);
        sum0 += __shfl_xor_sync(0xffffffffu, sum0, 2);
        sum1 += __shfl_xor_sync(0xffffffffu, sum1, 1);
        sum1 += __shfl_xor_sync(0xffffffffu, sum1, 2);
        if ((lane & 3) == 0) { halfsum[r0 * 2 + mh] = sum0; halfsum[r1 * 2 + mh] = sum1; }
        __syncthreads();
        if (tid < 64)
            rowsum[tid] = rowsum[tid] * corr[tid] + halfsum[tid * 2] + halfsum[tid * 2 + 1];

        // ---- rescale O ----
        float c0 = corr[r0], c1 = corr[r1];
#pragma unroll
        for (int dc = 0; dc < 4; dc++)
#pragma unroll
            for (int nj = 0; nj < 4; nj++) {
                o[dc][nj][0] *= c0; o[dc][nj][1] *= c0;
                o[dc][nj][2] *= c1; o[dc][nj][3] *= c1;
            }

        // ---- O += P @ V, d-chunks of 64 (V^T tiles reuse K buffers) ----
        for (int dc = 0; dc < 4; dc++) {
            __syncthreads();
#pragma unroll
            for (int it = 0; it < 8; it++) {
                int task = tid + 256 * it;
                int arr = task >> 10, idx = task & 1023;
                int r = idx >> 4, c8 = idx & 15;
                uint4 v = (arr ? vl4 : vh4)[(size_t)(dc * 64 + r) * 128 + (mbase >> 3) + c8];
                *(uint4*)&((arr ? KL : KH)[r * AT_PS + c8 * 8]) = v;
            }
            __syncthreads();
#pragma unroll
            for (int ks = 0; ks < 8; ks++) {
                uint32_t ph[4], pl[4];
                lda(ph, PH + qb * AT_PS + ks * 16, AT_PS, lane);
                lda(pl, PL + qb * AT_PS + ks * 16, AT_PS, lane);
#pragma unroll
                for (int nj = 0; nj < 4; nj++) {
                    uint32_t bh[2], bl[2];
                    ldb(bh, KH + (mh * 32 + nj * 8) * AT_PS + ks * 16, AT_PS, lane);
                    ldb(bl, KL + (mh * 32 + nj * 8) * AT_PS + ks * 16, AT_PS, lane);
                    mma16816(o[dc][nj], ph, bh);
                    mma16816(o[dc][nj], ph, bl);
                    mma16816(o[dc][nj], pl, bh);
                }
            }
        }
    }
    __syncthreads();

    // ---- epilogue ----
    const float i0 = 1.0f / rowsum[r0], i1 = 1.0f / rowsum[r1];
#pragma unroll
    for (int dc = 0; dc < 4; dc++)
#pragma unroll
        for (int nj = 0; nj < 4; nj++) {
            int col = dc * 64 + mh * 32 + nj * 8 + 2 * (lane & 3);
            float2 v0 = make_float2(o[dc][nj][0] * i0, o[dc][nj][1] * i0);
            float2 v1 = make_float2(o[dc][nj][2] * i1, o[dc][nj][3] * i1);
            *(float2*)&out[(size_t)(b * SEQ + qbase + r0) * DIM + col] = v0;
            *(float2*)&out[(size_t)(b * SEQ + qbase + r1) * DIM + col] = v1;
        }
}

// ---------------------------------------------------------------------------
extern "C" void kernel_launch(void* const* d_in, const int* in_sizes, int n_in,
                              void* d_out, int out_size)
{
    const float* traj = (const float*)d_in[0];
    const float* Wq = (const float*)d_in[1];
    const float* bq = (const float*)d_in[2];
    const float* Wk = (const float*)d_in[3];
    const float* bk = (const float*)d_in[4];
    const float* Wv = (const float*)d_in[5];
    const float* bv = (const float*)d_in[6];
    float* out = (float*)d_out;

    cudaFuncSetAttribute(proj_kernel, cudaFuncAttributeMaxDynamicSharedMemorySize, PJ_SMEM);
    cudaFuncSetAttribute(attn_kernel, cudaFuncAttributeMaxDynamicSharedMemorySize, AT_SMEM);

    proj_kernel<<<dim3(256, 2, 3), 256, PJ_SMEM>>>(traj, Wq, Wk, Wv, bq, bk, bv);
    vt_kernel<<<dim3(32, 8, 32), dim3(32, 8)>>>();
    attn_kernel<<<dim3(16, 32), 256, AT_SMEM>>>(out);
}

// round 10
// speedup vs baseline: 2.9042x; 1.1778x over previous
#include <cuda_runtime.h>
#include <cuda_fp16.h>
#include <cstdint>

#define BATCH 32
#define SEQ   1024
#define DIM   256
#define NROWS (BATCH * SEQ)

// static scratch: fp16 hi/lo pairs
__device__ __align__(256) __half g_x [2][(size_t)NROWS * DIM];  // traj split
__device__ __align__(256) __half g_w [2][3][DIM * DIM];         // weights split
__device__ __align__(256) __half g_q [2][(size_t)NROWS * DIM];
__device__ __align__(256) __half g_k [2][(size_t)NROWS * DIM];
__device__ __align__(256) __half g_v [2][(size_t)NROWS * DIM];
__device__ __align__(256) __half g_vt[2][(size_t)NROWS * DIM];  // [(b*256+d)*1024+m]

// ---------------- helpers ----------------
__device__ __forceinline__ uint32_t smem_u32(const void* p) {
    uint32_t a;
    asm("{ .reg .u64 t; cvta.to.shared.u64 t, %1; cvt.u32.u64 %0, t; }" : "=r"(a) : "l"(p));
    return a;
}
__device__ __forceinline__ void cpa16(uint32_t dst, const void* src) {
    asm volatile("cp.async.ca.shared.global [%0], [%1], 16;" :: "r"(dst), "l"(src));
}
#define CP_COMMIT() asm volatile("cp.async.commit_group;" ::: "memory")
#define CP_WAIT0()  asm volatile("cp.async.wait_group 0;" ::: "memory")

__device__ __forceinline__ void mma16816(float* d, const uint32_t* a, const uint32_t* b) {
    asm volatile("mma.sync.aligned.m16n8k16.row.col.f32.f16.f16.f32 "
        "{%0,%1,%2,%3}, {%4,%5,%6,%7}, {%8,%9}, {%0,%1,%2,%3};"
        : "+f"(d[0]), "+f"(d[1]), "+f"(d[2]), "+f"(d[3])
        : "r"(a[0]), "r"(a[1]), "r"(a[2]), "r"(a[3]), "r"(b[0]), "r"(b[1]));
}
__device__ __forceinline__ void lda(uint32_t* a, const __half* base, int S, int lane) {
    int r = lane >> 2, q = (lane & 3) * 2;
    a[0] = *(const uint32_t*)(base + r * S + q);
    a[1] = *(const uint32_t*)(base + (r + 8) * S + q);
    a[2] = *(const uint32_t*)(base + r * S + q + 8);
    a[3] = *(const uint32_t*)(base + (r + 8) * S + q + 8);
}
__device__ __forceinline__ void ldb(uint32_t* b, const __half* base, int S, int lane) {
    int r = lane >> 2, q = (lane & 3) * 2;
    b[0] = *(const uint32_t*)(base + r * S + q);
    b[1] = *(const uint32_t*)(base + r * S + q + 8);
}
__device__ __forceinline__ void splitf(float x, __half& h, __half& l) {
    h = __float2half_rn(x);
    l = __float2half_rn(x - __half2float(h));
}
__device__ __forceinline__ uint32_t packh(__half a, __half b) {
    __half2 h2 = __halves2half2(a, b);
    return *reinterpret_cast<uint32_t*>(&h2);
}

// ---------------- split kernels ----------------
__global__ __launch_bounds__(256) void split_x_kernel(const float* __restrict__ X) {
    size_t i = ((size_t)blockIdx.x * 256 + threadIdx.x) * 4;
    float4 v = *(const float4*)(X + i);
    __half h0, l0, h1, l1, h2, l2, h3, l3;
    splitf(v.x, h0, l0); splitf(v.y, h1, l1); splitf(v.z, h2, l2); splitf(v.w, h3, l3);
    *(uint2*)&g_x[0][i] = make_uint2(packh(h0, h1), packh(h2, h3));
    *(uint2*)&g_x[1][i] = make_uint2(packh(l0, l1), packh(l2, l3));
}
__global__ __launch_bounds__(256) void split_w_kernel(
    const float* __restrict__ Wq, const float* __restrict__ Wk, const float* __restrict__ Wv) {
    size_t i = ((size_t)blockIdx.x * 256 + threadIdx.x) * 4;
    int z = (int)(i >> 16);
    size_t off = i & 65535;
    const float* W = (z == 0) ? Wq : ((z == 1) ? Wk : Wv);
    float4 v = *(const float4*)(W + off);
    __half h0, l0, h1, l1, h2, l2, h3, l3;
    splitf(v.x, h0, l0); splitf(v.y, h1, l1); splitf(v.z, h2, l2); splitf(v.w, h3, l3);
    *(uint2*)&g_w[0][z][off] = make_uint2(packh(h0, h1), packh(h2, h3));
    *(uint2*)&g_w[1][z][off] = make_uint2(packh(l0, l1), packh(l2, l3));
}

// ---------------- projection: Y = X @ W^T + b (fp16-split 3-MMA) ----------------
#define PJ_S 72
#define PJ_SMEM (4 * 18432)
__global__ __launch_bounds__(256, 2) void proj_kernel(
    const float* __restrict__ bq, const float* __restrict__ bk, const float* __restrict__ bv)
{
    extern __shared__ char sm[];
    __half* AH = (__half*)(sm);
    __half* AL = (__half*)(sm + 18432);
    __half* BH = (__half*)(sm + 36864);
    __half* BL = (__half*)(sm + 55296);

    const int tid = threadIdx.x, lane = tid & 31, w = tid >> 5;
    const int wy = w >> 1, wx = w & 1;
    const int rbase = blockIdx.x * 128, cbase = blockIdx.y * 128, z = blockIdx.z;
    const float* bias = (z == 0) ? bq : ((z == 1) ? bk : bv);

    const uint4* xh4 = (const uint4*)(g_x[0]);
    const uint4* xl4 = (const uint4*)(g_x[1]);
    const uint4* wh4 = (const uint4*)(g_w[0][z]);
    const uint4* wl4 = (const uint4*)(g_w[1][z]);

    float acc[2][8][4];
#pragma unroll
    for (int mi = 0; mi < 2; mi++)
#pragma unroll
        for (int nj = 0; nj < 8; nj++)
#pragma unroll
            for (int c = 0; c < 4; c++) acc[mi][nj][c] = 0.f;

    for (int kc = 0; kc < 4; kc++) {
        __syncthreads();
#pragma unroll
        for (int it = 0; it < 4; it++) {
            int task = tid + 256 * it;           // 0..1023
            int r = task >> 3, c8 = task & 7;
            uint4 va = xh4[(size_t)(rbase + r) * 32 + kc * 8 + c8];
            uint4 vb = xl4[(size_t)(rbase + r) * 32 + kc * 8 + c8];
            uint4 vc = wh4[(size_t)(cbase + r) * 32 + kc * 8 + c8];
            uint4 vd = wl4[(size_t)(cbase + r) * 32 + kc * 8 + c8];
            *(uint4*)&AH[r * PJ_S + c8 * 8] = va;
            *(uint4*)&AL[r * PJ_S + c8 * 8] = vb;
            *(uint4*)&BH[r * PJ_S + c8 * 8] = vc;
            *(uint4*)&BL[r * PJ_S + c8 * 8] = vd;
        }
        __syncthreads();
#pragma unroll
        for (int ks = 0; ks < 4; ks++) {
            uint32_t ah[2][4], al[2][4];
#pragma unroll
            for (int mi = 0; mi < 2; mi++) {
                lda(ah[mi], AH + (wy * 32 + mi * 16) * PJ_S + ks * 16, PJ_S, lane);
                lda(al[mi], AL + (wy * 32 + mi * 16) * PJ_S + ks * 16, PJ_S, lane);
            }
#pragma unroll
            for (int nj = 0; nj < 8; nj++) {
                uint32_t bh[2], bl[2];
                ldb(bh, BH + (wx * 64 + nj * 8) * PJ_S + ks * 16, PJ_S, lane);
                ldb(bl, BL + (wx * 64 + nj * 8) * PJ_S + ks * 16, PJ_S, lane);
#pragma unroll
                for (int mi = 0; mi < 2; mi++) {
                    mma16816(acc[mi][nj], ah[mi], bh);
                    mma16816(acc[mi][nj], ah[mi], bl);
                    mma16816(acc[mi][nj], al[mi], bh);
                }
            }
        }
    }

    uint32_t* dh = (uint32_t*)((z == 0) ? g_q[0] : (z == 1) ? g_k[0] : g_v[0]);
    uint32_t* dl = (uint32_t*)((z == 0) ? g_q[1] : (z == 1) ? g_k[1] : g_v[1]);
#pragma unroll
    for (int mi = 0; mi < 2; mi++) {
        int rA = rbase + wy * 32 + mi * 16 + (lane >> 2);
#pragma unroll
        for (int nj = 0; nj < 8; nj++) {
            int col = cbase + wx * 64 + nj * 8 + 2 * (lane & 3);
            float b0 = __ldg(&bias[col]), b1 = __ldg(&bias[col + 1]);
            __half h0, l0, h1, l1;
            float y0 = acc[mi][nj][0] + b0, y1 = acc[mi][nj][1] + b1;
            splitf(y0, h0, l0); splitf(y1, h1, l1);
            dh[(size_t)rA * 128 + (col >> 1)] = packh(h0, h1);
            dl[(size_t)rA * 128 + (col >> 1)] = packh(l0, l1);
            float y2 = acc[mi][nj][2] + b0, y3 = acc[mi][nj][3] + b1;
            splitf(y2, h0, l0); splitf(y3, h1, l1);
            dh[(size_t)(rA + 8) * 128 + (col >> 1)] = packh(h0, h1);
            dl[(size_t)(rA + 8) * 128 + (col >> 1)] = packh(l0, l1);
        }
    }
}

// ---------------- V transpose ----------------
__global__ __launch_bounds__(256) void vt_kernel()
{
    __shared__ __half t0[32][33], t1[32][33];
    const int b = blockIdx.z, d0 = blockIdx.y * 32, m0 = blockIdx.x * 32;
    const int tx = threadIdx.x, ty = threadIdx.y;
#pragma unroll
    for (int i = 0; i < 4; i++) {
        int m = ty + 8 * i;
        size_t src = ((size_t)b * SEQ + m0 + m) * DIM + d0 + tx;
        t0[m][tx] = g_v[0][src];
        t1[m][tx] = g_v[1][src];
    }
    __syncthreads();
#pragma unroll
    for (int i = 0; i < 4; i++) {
        int d = ty + 8 * i;
        size_t dst = ((size_t)b * DIM + d0 + d) * SEQ + m0 + tx;
        g_vt[0][dst] = t0[tx][d];
        g_vt[1][dst] = t1[tx][d];
    }
}

// ---------------- attention: cp.async double-buffered flash ----------------
#define AT_QS 264
#define AT_KS 72
#define AT_PS 136
#define A_QH   0
#define A_QL   33792
#define A_BUF0 67584
#define BUFSZ  36864
#define A_PH   141312
#define A_PL   158720
#define A_ST   176128
#define AT_SMEM 178048   // A_ST + 1792 B of state, rounded up

__device__ __forceinline__ void issue_stage(uint32_t sb, int st, int tid,
    const uint4* kh4, const uint4* kl4, const uint4* vh4, const uint4* vl4)
{
    if (st < 64) {
        int mt2 = st >> 3, ph2 = st & 7;
        uint32_t bo = sb + A_BUF0 + (uint32_t)(st & 1) * BUFSZ;
        int mbase = mt2 * 128;
        if (ph2 < 4) {
            int dc = ph2;
#pragma unroll
            for (int it = 0; it < 8; it++) {
                int task = tid + 256 * it;           // 0..2047
                int arr = task >> 10, idx = task & 1023;
                int r = idx >> 3, c8 = idx & 7;
                const uint4* src = (arr ? kl4 : kh4) + (size_t)(mbase + r) * 32 + dc * 8 + c8;
                cpa16(bo + (uint32_t)arr * 18432 + (uint32_t)(r * AT_KS + c8 * 8) * 2, src);
            }
        } else {
            int dc = ph2 - 4;
#pragma unroll
            for (int it = 0; it < 8; it++) {
                int task = tid + 256 * it;
                int arr = task >> 10, idx = task & 1023;
                int r = idx >> 4, c8 = idx & 15;     // 64 rows x 16 c8
                const uint4* src = (arr ? vl4 : vh4) + (size_t)(dc * 64 + r) * 128 + (mbase >> 3) + c8;
                cpa16(bo + (uint32_t)arr * 18432 + (uint32_t)(r * AT_PS + c8 * 8) * 2, src);
            }
        }
    }
    CP_COMMIT();
}

__global__ __launch_bounds__(256, 1) void attn_kernel(float* __restrict__ out)
{
    extern __shared__ char sm[];
    const uint32_t sb = smem_u32(sm);
    __half* QH = (__half*)(sm + A_QH);
    __half* QL = (__half*)(sm + A_QL);
    __half* PH = (__half*)(sm + A_PH);
    __half* PL = (__half*)(sm + A_PL);
    float* rowmax  = (float*)(sm + A_ST);
    float* rowsum  = rowmax + 64;
    float* corr    = rowsum + 64;
    float* halfmax = corr + 64;    // [64][2]
    float* halfsum = halfmax + 128;

    const int b = blockIdx.y, qbase = blockIdx.x * 64;
    const int tid = threadIdx.x, lane = tid & 31, w = tid >> 5;
    const int qb = (w >> 1) * 16, mh = w & 1;
    const int r0 = qb + (lane >> 2), r1 = r0 + 8;

    const uint4* kh4 = (const uint4*)(g_k[0] + (size_t)b * SEQ * DIM);
    const uint4* kl4 = (const uint4*)(g_k[1] + (size_t)b * SEQ * DIM);
    const uint4* vh4 = (const uint4*)(g_vt[0] + (size_t)b * DIM * SEQ);
    const uint4* vl4 = (const uint4*)(g_vt[1] + (size_t)b * DIM * SEQ);

    // stage 0 prefetch first, then Q tile while it flies
    issue_stage(sb, 0, tid, kh4, kl4, vh4, vl4);

    const uint4* qh4 = (const uint4*)(g_q[0] + (size_t)(b * SEQ + qbase) * DIM);
    const uint4* ql4 = (const uint4*)(g_q[1] + (size_t)(b * SEQ + qbase) * DIM);
#pragma unroll
    for (int it = 0; it < 16; it++) {
        int task = tid + 256 * it;
        int arr = task >> 11, idx = task & 2047;
        int r = idx >> 5, c8 = idx & 31;
        uint4 v = (arr ? ql4 : qh4)[r * 32 + c8];
        *(uint4*)&((arr ? QL : QH)[r * AT_QS + c8 * 8]) = v;
    }
    if (tid < 64) { rowmax[tid] = -1e30f; rowsum[tid] = 0.f; }

    float o[4][4][4];
#pragma unroll
    for (int dc = 0; dc < 4; dc++)
#pragma unroll
        for (int nj = 0; nj < 4; nj++)
#pragma unroll
            for (int c = 0; c < 4; c++) o[dc][nj][c] = 0.f;

    int st = 0;
    for (int mt = 0; mt < 8; mt++) {
        float s[8][4];
#pragma unroll
        for (int nj = 0; nj < 8; nj++)
#pragma unroll
            for (int c = 0; c < 4; c++) s[nj][c] = 0.f;

        // ---- S = Q K^T: 4 K-chunk stages ----
        for (int dc = 0; dc < 4; dc++) {
            CP_WAIT0();
            __syncthreads();
            issue_stage(sb, st + 1, tid, kh4, kl4, vh4, vl4);
            const __half* KH = (const __half*)(sm + A_BUF0 + (st & 1) * BUFSZ);
            const __half* KL = (const __half*)(sm + A_BUF0 + (st & 1) * BUFSZ + 18432);
#pragma unroll
            for (int ks = 0; ks < 4; ks++) {
                uint32_t ah[4], al[4];
                lda(ah, QH + qb * AT_QS + dc * 64 + ks * 16, AT_QS, lane);
                lda(al, QL + qb * AT_QS + dc * 64 + ks * 16, AT_QS, lane);
#pragma unroll
                for (int nj = 0; nj < 8; nj++) {
                    uint32_t bh[2], bl[2];
                    ldb(bh, KH + (mh * 64 + nj * 8) * AT_KS + ks * 16, AT_KS, lane);
                    ldb(bl, KL + (mh * 64 + nj * 8) * AT_KS + ks * 16, AT_KS, lane);
                    mma16816(s[nj], ah, bh);
                    mma16816(s[nj], ah, bl);
                    mma16816(s[nj], al, bh);
                }
            }
            st++;
        }

        // ---- online softmax ----
        float mx0 = -1e30f, mx1 = -1e30f;
#pragma unroll
        for (int nj = 0; nj < 8; nj++) {
            mx0 = fmaxf(mx0, fmaxf(s[nj][0], s[nj][1]));
            mx1 = fmaxf(mx1, fmaxf(s[nj][2], s[nj][3]));
        }
        mx0 = fmaxf(mx0, __shfl_xor_sync(0xffffffffu, mx0, 1));
        mx0 = fmaxf(mx0, __shfl_xor_sync(0xffffffffu, mx0, 2));
        mx1 = fmaxf(mx1, __shfl_xor_sync(0xffffffffu, mx1, 1));
        mx1 = fmaxf(mx1, __shfl_xor_sync(0xffffffffu, mx1, 2));
        if ((lane & 3) == 0) { halfmax[r0 * 2 + mh] = mx0; halfmax[r1 * 2 + mh] = mx1; }
        __syncthreads();
        if (tid < 64) {
            float mo = rowmax[tid];
            float mn = fmaxf(mo, fmaxf(halfmax[tid * 2], halfmax[tid * 2 + 1]));
            rowmax[tid] = mn;
            corr[tid] = __expf(mo - mn);
        }
        __syncthreads();
        float m0 = rowmax[r0], m1 = rowmax[r1];
        float sum0 = 0.f, sum1 = 0.f;
#pragma unroll
        for (int nj = 0; nj < 8; nj++) {
            int cc = mh * 64 + nj * 8 + 2 * (lane & 3);
            float e0 = __expf(s[nj][0] - m0), e1 = __expf(s[nj][1] - m0);
            float e2 = __expf(s[nj][2] - m1), e3 = __expf(s[nj][3] - m1);
            sum0 += e0 + e1; sum1 += e2 + e3;
            __half h0, l0, h1, l1;
            splitf(e0, h0, l0); splitf(e1, h1, l1);
            *(uint32_t*)&PH[r0 * AT_PS + cc] = packh(h0, h1);
            *(uint32_t*)&PL[r0 * AT_PS + cc] = packh(l0, l1);
            splitf(e2, h0, l0); splitf(e3, h1, l1);
            *(uint32_t*)&PH[r1 * AT_PS + cc] = packh(h0, h1);
            *(uint32_t*)&PL[r1 * AT_PS + cc] = packh(l0, l1);
        }
        sum0 += __shfl_xor_sync(0xffffffffu, sum0, 1);
        sum0 += __shfl_xor_sync(0xffffffffu, sum0, 2);
        sum1 += __shfl_xor_sync(0xffffffffu, sum1, 1);
        sum1 += __shfl_xor_sync(0xffffffffu, sum1, 2);
        if ((lane & 3) == 0) { halfsum[r0 * 2 + mh] = sum0; halfsum[r1 * 2 + mh] = sum1; }
        __syncthreads();
        if (tid < 64)
            rowsum[tid] = rowsum[tid] * corr[tid] + halfsum[tid * 2] + halfsum[tid * 2 + 1];

        // ---- rescale O ----
        float c0 = corr[r0], c1 = corr[r1];
#pragma unroll
        for (int dc = 0; dc < 4; dc++)
#pragma unroll
            for (int nj = 0; nj < 4; nj++) {
                o[dc][nj][0] *= c0; o[dc][nj][1] *= c0;
                o[dc][nj][2] *= c1; o[dc][nj][3] *= c1;
            }

        // ---- O += P @ V: 4 V-chunk stages ----
        for (int dc = 0; dc < 4; dc++) {
            CP_WAIT0();
            __syncthreads();
            issue_stage(sb, st + 1, tid, kh4, kl4, vh4, vl4);
            const __half* VH = (const __half*)(sm + A_BUF0 + (st & 1) * BUFSZ);
            const __half* VL = (const __half*)(sm + A_BUF0 + (st & 1) * BUFSZ + 18432);
#pragma unroll
            for (int ks = 0; ks < 8; ks++) {
                uint32_t ph[4], pl[4];
                lda(ph, PH + qb * AT_PS + ks * 16, AT_PS, lane);
                lda(pl, PL + qb * AT_PS + ks * 16, AT_PS, lane);
#pragma unroll
                for (int nj = 0; nj < 4; nj++) {
                    uint32_t bh[2], bl[2];
                    ldb(bh, VH + (mh * 32 + nj * 8) * AT_PS + ks * 16, AT_PS, lane);
                    ldb(bl, VL + (mh * 32 + nj * 8) * AT_PS + ks * 16, AT_PS, lane);
                    mma16816(o[dc][nj], ph, bh);
                    mma16816(o[dc][nj], ph, bl);
                    mma16816(o[dc][nj], pl, bh);
                }
            }
            st++;
        }
    }
    __syncthreads();

    // ---- epilogue ----
    const float i0 = 1.0f / rowsum[r0], i1 = 1.0f / rowsum[r1];
#pragma unroll
    for (int dc = 0; dc < 4; dc++)
#pragma unroll
        for (int nj = 0; nj < 4; nj++) {
            int col = dc * 64 + mh * 32 + nj * 8 + 2 * (lane & 3);
            float2 v0 = make_float2(o[dc][nj][0] * i0, o[dc][nj][1] * i0);
            float2 v1 = make_float2(o[dc][nj][2] * i1, o[dc][nj][3] * i1);
            *(float2*)&out[(size_t)(b * SEQ + qbase + r0) * DIM + col] = v0;
            *(float2*)&out[(size_t)(b * SEQ + qbase + r1) * DIM + col] = v1;
        }
}

// ---------------------------------------------------------------------------
extern "C" void kernel_launch(void* const* d_in, const int* in_sizes, int n_in,
                              void* d_out, int out_size)
{
    const float* traj = (const float*)d_in[0];
    const float* Wq = (const float*)d_in[1];
    const float* bq = (const float*)d_in[2];
    const float* Wk = (const float*)d_in[3];
    const float* bk = (const float*)d_in[4];
    const float* Wv = (const float*)d_in[5];
    const float* bv = (const float*)d_in[6];
    float* out = (float*)d_out;

    cudaFuncSetAttribute(proj_kernel, cudaFuncAttributeMaxDynamicSharedMemorySize, PJ_SMEM);
    cudaFuncSetAttribute(attn_kernel, cudaFuncAttributeMaxDynamicSharedMemorySize, AT_SMEM);

    split_x_kernel<<<8192, 256>>>(traj);
    split_w_kernel<<<192, 256>>>(Wq, Wk, Wv);
    proj_kernel<<<dim3(256, 2, 3), 256, PJ_SMEM>>>(bq, bk, bv);
    vt_kernel<<<dim3(32, 8, 32), dim3(32, 8)>>>();
    attn_kernel<<<dim3(16, 32), 256, AT_SMEM>>>(out);
}

// round 12
// speedup vs baseline: 3.4240x; 1.1790x over previous
#include <cuda_runtime.h>
#include <cuda_fp16.h>
#include <cstdint>

#define BATCH 32
#define SEQ   1024
#define DIM   256
#define NROWS (BATCH * SEQ)

// static scratch: fp16 hi/lo pairs
__device__ __align__(256) __half g_x [2][(size_t)NROWS * DIM];  // traj split
__device__ __align__(256) __half g_w [2][3][DIM * DIM];         // weights split
__device__ __align__(256) __half g_q [2][(size_t)NROWS * DIM];
__device__ __align__(256) __half g_k [2][(size_t)NROWS * DIM];
__device__ __align__(256) __half g_v [2][(size_t)NROWS * DIM];
__device__ __align__(256) __half g_vt[2][(size_t)NROWS * DIM];  // [(b*256+d)*1024+m]

// ---------------- helpers ----------------
__device__ __forceinline__ uint32_t smem_u32(const void* p) {
    uint32_t a;
    asm("{ .reg .u64 t; cvta.to.shared.u64 t, %1; cvt.u32.u64 %0, t; }" : "=r"(a) : "l"(p));
    return a;
}
__device__ __forceinline__ void cpa16(uint32_t dst, const void* src) {
    asm volatile("cp.async.ca.shared.global [%0], [%1], 16;" :: "r"(dst), "l"(src));
}
#define CP_COMMIT() asm volatile("cp.async.commit_group;" ::: "memory")
#define CP_WAIT0()  asm volatile("cp.async.wait_group 0;" ::: "memory")

__device__ __forceinline__ void mma16816(float* d, const uint32_t* a, const uint32_t* b) {
    asm volatile("mma.sync.aligned.m16n8k16.row.col.f32.f16.f16.f32 "
        "{%0,%1,%2,%3}, {%4,%5,%6,%7}, {%8,%9}, {%0,%1,%2,%3};"
        : "+f"(d[0]), "+f"(d[1]), "+f"(d[2]), "+f"(d[3])
        : "r"(a[0]), "r"(a[1]), "r"(a[2]), "r"(a[3]), "r"(b[0]), "r"(b[1]));
}
// ldmatrix: A fragment (m16xk16) — 4 8x8 matrices; address groups give a0..a3
__device__ __forceinline__ void ldm_a(uint32_t* a, uint32_t addr) {
    asm volatile("ldmatrix.sync.aligned.m8n8.x4.shared.b16 {%0,%1,%2,%3}, [%4];"
        : "=r"(a[0]), "=r"(a[1]), "=r"(a[2]), "=r"(a[3]) : "r"(addr));
}
// ldmatrix: B fragment (k16xn8) — 2 8x8 matrices
__device__ __forceinline__ void ldm_b(uint32_t* b, uint32_t addr) {
    asm volatile("ldmatrix.sync.aligned.m8n8.x2.shared.b16 {%0,%1}, [%2];"
        : "=r"(b[0]), "=r"(b[1]) : "r"(addr));
}
// per-thread byte offsets for ldmatrix address groups (S in halfs)
__device__ __forceinline__ uint32_t aoff_b(int lane, int S) {
    return 2u * (uint32_t)((lane < 16) ? lane * S : (lane - 16) * S + 8);
}
__device__ __forceinline__ uint32_t boff_b(int lane, int S) {
    return 2u * (uint32_t)((lane & 7) * S + ((lane >> 3) & 1) * 8);
}
__device__ __forceinline__ void splitf(float x, __half& h, __half& l) {
    h = __float2half_rn(x);
    l = __float2half_rn(x - __half2float(h));
}
__device__ __forceinline__ uint32_t packh(__half a, __half b) {
    __half2 h2 = __halves2half2(a, b);
    return *reinterpret_cast<uint32_t*>(&h2);
}

// ---------------- split kernels ----------------
__global__ __launch_bounds__(256) void split_x_kernel(const float* __restrict__ X) {
    size_t i = ((size_t)blockIdx.x * 256 + threadIdx.x) * 4;
    float4 v = *(const float4*)(X + i);
    __half h0, l0, h1, l1, h2, l2, h3, l3;
    splitf(v.x, h0, l0); splitf(v.y, h1, l1); splitf(v.z, h2, l2); splitf(v.w, h3, l3);
    *(uint2*)&g_x[0][i] = make_uint2(packh(h0, h1), packh(h2, h3));
    *(uint2*)&g_x[1][i] = make_uint2(packh(l0, l1), packh(l2, l3));
}
__global__ __launch_bounds__(256) void split_w_kernel(
    const float* __restrict__ Wq, const float* __restrict__ Wk, const float* __restrict__ Wv) {
    size_t i = ((size_t)blockIdx.x * 256 + threadIdx.x) * 4;
    int z = (int)(i >> 16);
    size_t off = i & 65535;
    const float* W = (z == 0) ? Wq : ((z == 1) ? Wk : Wv);
    float4 v = *(const float4*)(W + off);
    __half h0, l0, h1, l1, h2, l2, h3, l3;
    splitf(v.x, h0, l0); splitf(v.y, h1, l1); splitf(v.z, h2, l2); splitf(v.w, h3, l3);
    *(uint2*)&g_w[0][z][off] = make_uint2(packh(h0, h1), packh(h2, h3));
    *(uint2*)&g_w[1][z][off] = make_uint2(packh(l0, l1), packh(l2, l3));
}

// ---------------- projection: Y = X @ W^T + b (fp16-split 3-MMA) ----------------
#define PJ_S 72
#define PJ_SMEM (4 * 18432)
__global__ __launch_bounds__(256, 2) void proj_kernel(
    const float* __restrict__ bq, const float* __restrict__ bk, const float* __restrict__ bv)
{
    extern __shared__ char sm[];
    __half* AH = (__half*)(sm);
    __half* AL = (__half*)(sm + 18432);
    __half* BH = (__half*)(sm + 36864);
    __half* BL = (__half*)(sm + 55296);

    const int tid = threadIdx.x, lane = tid & 31, w = tid >> 5;
    const int wy = w >> 1, wx = w & 1;
    const int rbase = blockIdx.x * 128, cbase = blockIdx.y * 128, z = blockIdx.z;
    const float* bias = (z == 0) ? bq : ((z == 1) ? bk : bv);

    const uint32_t sbp = smem_u32(sm);
    const uint32_t aoff = aoff_b(lane, PJ_S), boff = boff_b(lane, PJ_S);

    const uint4* xh4 = (const uint4*)(g_x[0]);
    const uint4* xl4 = (const uint4*)(g_x[1]);
    const uint4* wh4 = (const uint4*)(g_w[0][z]);
    const uint4* wl4 = (const uint4*)(g_w[1][z]);

    float acc[2][8][4];
#pragma unroll
    for (int mi = 0; mi < 2; mi++)
#pragma unroll
        for (int nj = 0; nj < 8; nj++)
#pragma unroll
            for (int c = 0; c < 4; c++) acc[mi][nj][c] = 0.f;

    for (int kc = 0; kc < 4; kc++) {
        __syncthreads();
#pragma unroll
        for (int it = 0; it < 4; it++) {
            int task = tid + 256 * it;           // 0..1023
            int r = task >> 3, c8 = task & 7;
            uint4 va = xh4[(size_t)(rbase + r) * 32 + kc * 8 + c8];
            uint4 vb = xl4[(size_t)(rbase + r) * 32 + kc * 8 + c8];
            uint4 vc = wh4[(size_t)(cbase + r) * 32 + kc * 8 + c8];
            uint4 vd = wl4[(size_t)(cbase + r) * 32 + kc * 8 + c8];
            *(uint4*)&AH[r * PJ_S + c8 * 8] = va;
            *(uint4*)&AL[r * PJ_S + c8 * 8] = vb;
            *(uint4*)&BH[r * PJ_S + c8 * 8] = vc;
            *(uint4*)&BL[r * PJ_S + c8 * 8] = vd;
        }
        __syncthreads();
#pragma unroll
        for (int ks = 0; ks < 4; ks++) {
            uint32_t ah[2][4], al[2][4];
#pragma unroll
            for (int mi = 0; mi < 2; mi++) {
                uint32_t ab = sbp + 2u * (uint32_t)((wy * 32 + mi * 16) * PJ_S + ks * 16) + aoff;
                ldm_a(ah[mi], ab);
                ldm_a(al[mi], ab + 18432);
            }
#pragma unroll
            for (int nj = 0; nj < 8; nj++) {
                uint32_t bh[2], bl[2];
                uint32_t bb = sbp + 36864 + 2u * (uint32_t)((wx * 64 + nj * 8) * PJ_S + ks * 16) + boff;
                ldm_b(bh, bb);
                ldm_b(bl, bb + 18432);
#pragma unroll
                for (int mi = 0; mi < 2; mi++) {
                    mma16816(acc[mi][nj], ah[mi], bh);
                    mma16816(acc[mi][nj], ah[mi], bl);
                    mma16816(acc[mi][nj], al[mi], bh);
                }
            }
        }
    }

    uint32_t* dh = (uint32_t*)((z == 0) ? g_q[0] : (z == 1) ? g_k[0] : g_v[0]);
    uint32_t* dl = (uint32_t*)((z == 0) ? g_q[1] : (z == 1) ? g_k[1] : g_v[1]);
#pragma unroll
    for (int mi = 0; mi < 2; mi++) {
        int rA = rbase + wy * 32 + mi * 16 + (lane >> 2);
#pragma unroll
        for (int nj = 0; nj < 8; nj++) {
            int col = cbase + wx * 64 + nj * 8 + 2 * (lane & 3);
            float b0 = __ldg(&bias[col]), b1 = __ldg(&bias[col + 1]);
            __half h0, l0, h1, l1;
            float y0 = acc[mi][nj][0] + b0, y1 = acc[mi][nj][1] + b1;
            splitf(y0, h0, l0); splitf(y1, h1, l1);
            dh[(size_t)rA * 128 + (col >> 1)] = packh(h0, h1);
            dl[(size_t)rA * 128 + (col >> 1)] = packh(l0, l1);
            float y2 = acc[mi][nj][2] + b0, y3 = acc[mi][nj][3] + b1;
            splitf(y2, h0, l0); splitf(y3, h1, l1);
            dh[(size_t)(rA + 8) * 128 + (col >> 1)] = packh(h0, h1);
            dl[(size_t)(rA + 8) * 128 + (col >> 1)] = packh(l0, l1);
        }
    }
}

// ---------------- V transpose ----------------
__global__ __launch_bounds__(256) void vt_kernel()
{
    __shared__ __half t0[32][33], t1[32][33];
    const int b = blockIdx.z, d0 = blockIdx.y * 32, m0 = blockIdx.x * 32;
    const int tx = threadIdx.x, ty = threadIdx.y;
#pragma unroll
    for (int i = 0; i < 4; i++) {
        int m = ty + 8 * i;
        size_t src = ((size_t)b * SEQ + m0 + m) * DIM + d0 + tx;
        t0[m][tx] = g_v[0][src];
        t1[m][tx] = g_v[1][src];
    }
    __syncthreads();
#pragma unroll
    for (int i = 0; i < 4; i++) {
        int d = ty + 8 * i;
        size_t dst = ((size_t)b * DIM + d0 + d) * SEQ + m0 + tx;
        g_vt[0][dst] = t0[tx][d];
        g_vt[1][dst] = t1[tx][d];
    }
}

// ---------------- attention: cp.async double-buffered flash + ldmatrix ----------------
#define AT_QS 264
#define AT_KS 72
#define AT_PS 136
#define A_QH   0
#define A_QL   33792
#define A_BUF0 67584
#define BUFSZ  36864
#define A_PH   141312
#define A_PL   158720
#define A_ST   176128
#define AT_SMEM 178048   // A_ST + 1792 B of state

__device__ __forceinline__ void issue_stage(uint32_t sb, int st, int tid,
    const uint4* kh4, const uint4* kl4, const uint4* vh4, const uint4* vl4)
{
    if (st < 64) {
        int mt2 = st >> 3, ph2 = st & 7;
        uint32_t bo = sb + A_BUF0 + (uint32_t)(st & 1) * BUFSZ;
        int mbase = mt2 * 128;
        if (ph2 < 4) {
            int dc = ph2;
#pragma unroll
            for (int it = 0; it < 8; it++) {
                int task = tid + 256 * it;           // 0..2047
                int arr = task >> 10, idx = task & 1023;
                int r = idx >> 3, c8 = idx & 7;
                const uint4* src = (arr ? kl4 : kh4) + (size_t)(mbase + r) * 32 + dc * 8 + c8;
                cpa16(bo + (uint32_t)arr * 18432 + (uint32_t)(r * AT_KS + c8 * 8) * 2, src);
            }
        } else {
            int dc = ph2 - 4;
#pragma unroll
            for (int it = 0; it < 8; it++) {
                int task = tid + 256 * it;
                int arr = task >> 10, idx = task & 1023;
                int r = idx >> 4, c8 = idx & 15;     // 64 rows x 16 c8
                const uint4* src = (arr ? vl4 : vh4) + (size_t)(dc * 64 + r) * 128 + (mbase >> 3) + c8;
                cpa16(bo + (uint32_t)arr * 18432 + (uint32_t)(r * AT_PS + c8 * 8) * 2, src);
            }
        }
    }
    CP_COMMIT();
}

__global__ __launch_bounds__(256, 1) void attn_kernel(float* __restrict__ out)
{
    extern __shared__ char sm[];
    const uint32_t sb = smem_u32(sm);
    __half* QH = (__half*)(sm + A_QH);
    __half* QL = (__half*)(sm + A_QL);
    __half* PH = (__half*)(sm + A_PH);
    __half* PL = (__half*)(sm + A_PL);
    float* rowmax  = (float*)(sm + A_ST);
    float* rowsum  = rowmax + 64;
    float* corr    = rowsum + 64;
    float* halfmax = corr + 64;    // [64][2]
    float* halfsum = halfmax + 128;

    const int b = blockIdx.y, qbase = blockIdx.x * 64;
    const int tid = threadIdx.x, lane = tid & 31, w = tid >> 5;
    const int qb = (w >> 1) * 16, mh = w & 1;
    const int r0 = qb + (lane >> 2), r1 = r0 + 8;

    // ldmatrix per-thread address offsets
    const uint32_t aQ = sb + A_QH + 2u * (uint32_t)(qb * AT_QS) + aoff_b(lane, AT_QS);
    const uint32_t aP = sb + A_PH + 2u * (uint32_t)(qb * AT_PS) + aoff_b(lane, AT_PS);
    const uint32_t bK = boff_b(lane, AT_KS);
    const uint32_t bV = boff_b(lane, AT_PS);

    const uint4* kh4 = (const uint4*)(g_k[0] + (size_t)b * SEQ * DIM);
    const uint4* kl4 = (const uint4*)(g_k[1] + (size_t)b * SEQ * DIM);
    const uint4* vh4 = (const uint4*)(g_vt[0] + (size_t)b * DIM * SEQ);
    const uint4* vl4 = (const uint4*)(g_vt[1] + (size_t)b * DIM * SEQ);

    issue_stage(sb, 0, tid, kh4, kl4, vh4, vl4);

    const uint4* qh4 = (const uint4*)(g_q[0] + (size_t)(b * SEQ + qbase) * DIM);
    const uint4* ql4 = (const uint4*)(g_q[1] + (size_t)(b * SEQ + qbase) * DIM);
#pragma unroll
    for (int it = 0; it < 16; it++) {
        int task = tid + 256 * it;
        int arr = task >> 11, idx = task & 2047;
        int r = idx >> 5, c8 = idx & 31;
        uint4 v = (arr ? ql4 : qh4)[r * 32 + c8];
        *(uint4*)&((arr ? QL : QH)[r * AT_QS + c8 * 8]) = v;
    }
    if (tid < 64) { rowmax[tid] = -1e30f; rowsum[tid] = 0.f; }

    float o[4][4][4];
#pragma unroll
    for (int dc = 0; dc < 4; dc++)
#pragma unroll
        for (int nj = 0; nj < 4; nj++)
#pragma unroll
            for (int c = 0; c < 4; c++) o[dc][nj][c] = 0.f;

    int st = 0;
    for (int mt = 0; mt < 8; mt++) {
        float s[8][4];
#pragma unroll
        for (int nj = 0; nj < 8; nj++)
#pragma unroll
            for (int c = 0; c < 4; c++) s[nj][c] = 0.f;

        // ---- S = Q K^T: 4 K-chunk stages ----
        for (int dc = 0; dc < 4; dc++) {
            CP_WAIT0();
            __syncthreads();
            issue_stage(sb, st + 1, tid, kh4, kl4, vh4, vl4);
            const uint32_t kb = sb + A_BUF0 + (uint32_t)(st & 1) * BUFSZ;
#pragma unroll
            for (int ks = 0; ks < 4; ks++) {
                uint32_t ah[4], al[4];
                uint32_t ab = aQ + 2u * (uint32_t)(dc * 64 + ks * 16);
                ldm_a(ah, ab);
                ldm_a(al, ab + 33792);
#pragma unroll
                for (int nj = 0; nj < 8; nj++) {
                    uint32_t bh[2], bl[2];
                    uint32_t bb = kb + 2u * (uint32_t)((mh * 64 + nj * 8) * AT_KS + ks * 16) + bK;
                    ldm_b(bh, bb);
                    ldm_b(bl, bb + 18432);
                    mma16816(s[nj], ah, bh);
                    mma16816(s[nj], ah, bl);
                    mma16816(s[nj], al, bh);
                }
            }
            st++;
        }

        // ---- online softmax ----
        float mx0 = -1e30f, mx1 = -1e30f;
#pragma unroll
        for (int nj = 0; nj < 8; nj++) {
            mx0 = fmaxf(mx0, fmaxf(s[nj][0], s[nj][1]));
            mx1 = fmaxf(mx1, fmaxf(s[nj][2], s[nj][3]));
        }
        mx0 = fmaxf(mx0, __shfl_xor_sync(0xffffffffu, mx0, 1));
        mx0 = fmaxf(mx0, __shfl_xor_sync(0xffffffffu, mx0, 2));
        mx1 = fmaxf(mx1, __shfl_xor_sync(0xffffffffu, mx1, 1));
        mx1 = fmaxf(mx1, __shfl_xor_sync(0xffffffffu, mx1, 2));
        if ((lane & 3) == 0) { halfmax[r0 * 2 + mh] = mx0; halfmax[r1 * 2 + mh] = mx1; }
        __syncthreads();
        if (tid < 64) {
            float mo = rowmax[tid];
            float mn = fmaxf(mo, fmaxf(halfmax[tid * 2], halfmax[tid * 2 + 1]));
            rowmax[tid] = mn;
            corr[tid] = __expf(mo - mn);
        }
        __syncthreads();
        float m0 = rowmax[r0], m1 = rowmax[r1];
        float sum0 = 0.f, sum1 = 0.f;
#pragma unroll
        for (int nj = 0; nj < 8; nj++) {
            int cc = mh * 64 + nj * 8 + 2 * (lane & 3);
            float e0 = __expf(s[nj][0] - m0), e1 = __expf(s[nj][1] - m0);
            float e2 = __expf(s[nj][2] - m1), e3 = __expf(s[nj][3] - m1);
            sum0 += e0 + e1; sum1 += e2 + e3;
            __half h0, l0, h1, l1;
            splitf(e0, h0, l0); splitf(e1, h1, l1);
            *(uint32_t*)&PH[r0 * AT_PS + cc] = packh(h0, h1);
            *(uint32_t*)&PL[r0 * AT_PS + cc] = packh(l0, l1);
            splitf(e2, h0, l0); splitf(e3, h1, l1);
            *(uint32_t*)&PH[r1 * AT_PS + cc] = packh(h0, h1);
            *(uint32_t*)&PL[r1 * AT_PS + cc] = packh(l0, l1);
        }
        sum0 += __shfl_xor_sync(0xffffffffu, sum0, 1);
        sum0 += __shfl_xor_sync(0xffffffffu, sum0, 2);
        sum1 += __shfl_xor_sync(0xffffffffu, sum1, 1);
        sum1 += __shfl_xor_sync(0xffffffffu, sum1, 2);
        if ((lane & 3) == 0) { halfsum[r0 * 2 + mh] = sum0; halfsum[r1 * 2 + mh] = sum1; }
        __syncthreads();
        if (tid < 64)
            rowsum[tid] = rowsum[tid] * corr[tid] + halfsum[tid * 2] + halfsum[tid * 2 + 1];

        // ---- rescale O ----
        float c0 = corr[r0], c1 = corr[r1];
#pragma unroll
        for (int dc = 0; dc < 4; dc++)
#pragma unroll
            for (int nj = 0; nj < 4; nj++) {
                o[dc][nj][0] *= c0; o[dc][nj][1] *= c0;
                o[dc][nj][2] *= c1; o[dc][nj][3] *= c1;
            }

        // ---- O += P @ V: 4 V-chunk stages ----
        for (int dc = 0; dc < 4; dc++) {
            CP_WAIT0();
            __syncthreads();
            issue_stage(sb, st + 1, tid, kh4, kl4, vh4, vl4);
            const uint32_t vb = sb + A_BUF0 + (uint32_t)(st & 1) * BUFSZ;
#pragma unroll
            for (int ks = 0; ks < 8; ks++) {
                uint32_t ph[4], pl[4];
                uint32_t ab = aP + 2u * (uint32_t)(ks * 16);
                ldm_a(ph, ab);
                ldm_a(pl, ab + 17408);
#pragma unroll
                for (int nj = 0; nj < 4; nj++) {
                    uint32_t bh[2], bl[2];
                    uint32_t bb = vb + 2u * (uint32_t)((mh * 32 + nj * 8) * AT_PS + ks * 16) + bV;
                    ldm_b(bh, bb);
                    ldm_b(bl, bb + 18432);
                    mma16816(o[dc][nj], ph, bh);
                    mma16816(o[dc][nj], ph, bl);
                    mma16816(o[dc][nj], pl, bh);
                }
            }
            st++;
        }
    }
    __syncthreads();

    // ---- epilogue ----
    const float i0 = 1.0f / rowsum[r0], i1 = 1.0f / rowsum[r1];
#pragma unroll
    for (int dc = 0; dc < 4; dc++)
#pragma unroll
        for (int nj = 0; nj < 4; nj++) {
            int col = dc * 64 + mh * 32 + nj * 8 + 2 * (lane & 3);
            float2 v0 = make_float2(o[dc][nj][0] * i0, o[dc][nj][1] * i0);
            float2 v1 = make_float2(o[dc][nj][2] * i1, o[dc][nj][3] * i1);
            *(float2*)&out[(size_t)(b * SEQ + qbase + r0) * DIM + col] = v0;
            *(float2*)&out[(size_t)(b * SEQ + qbase + r1) * DIM + col] = v1;
        }
}

// ---------------------------------------------------------------------------
extern "C" void kernel_launch(void* const* d_in, const int* in_sizes, int n_in,
                              void* d_out, int out_size)
{
    const float* traj = (const float*)d_in[0];
    const float* Wq = (const float*)d_in[1];
    const float* bq = (const float*)d_in[2];
    const float* Wk = (const float*)d_in[3];
    const float* bk = (const float*)d_in[4];
    const float* Wv = (const float*)d_in[5];
    const float* bv = (const float*)d_in[6];
    float* out = (float*)d_out;

    cudaFuncSetAttribute(proj_kernel, cudaFuncAttributeMaxDynamicSharedMemorySize, PJ_SMEM);
    cudaFuncSetAttribute(attn_kernel, cudaFuncAttributeMaxDynamicSharedMemorySize, AT_SMEM);

    split_x_kernel<<<8192, 256>>>(traj);
    split_w_kernel<<<192, 256>>>(Wq, Wk, Wv);
    proj_kernel<<<dim3(256, 2, 3), 256, PJ_SMEM>>>(bq, bk, bv);
    vt_kernel<<<dim3(32, 8, 32), dim3(32, 8)>>>();
    attn_kernel<<<dim3(16, 32), 256, AT_SMEM>>>(out);
}

// round 13
// speedup vs baseline: 3.6332x; 1.0611x over previous
#include <cuda_runtime.h>
#include <cuda_fp16.h>
#include <cstdint>

#define BATCH 32
#define SEQ   1024
#define DIM   256
#define NROWS (BATCH * SEQ)

// static scratch: fp16 hi/lo pairs
__device__ __align__(256) __half g_x [2][(size_t)NROWS * DIM];  // traj split
__device__ __align__(256) __half g_w [2][3][DIM * DIM];         // weights split
__device__ __align__(256) __half g_q [2][(size_t)NROWS * DIM];
__device__ __align__(256) __half g_k [2][(size_t)NROWS * DIM];
__device__ __align__(256) __half g_vt[2][(size_t)NROWS * DIM];  // [(b*256+d)*1024+m]

// ---------------- helpers ----------------
__device__ __forceinline__ uint32_t smem_u32(const void* p) {
    uint32_t a;
    asm("{ .reg .u64 t; cvta.to.shared.u64 t, %1; cvt.u32.u64 %0, t; }" : "=r"(a) : "l"(p));
    return a;
}
__device__ __forceinline__ void cpa16(uint32_t dst, const void* src) {
    asm volatile("cp.async.ca.shared.global [%0], [%1], 16;" :: "r"(dst), "l"(src));
}
#define CP_COMMIT() asm volatile("cp.async.commit_group;" ::: "memory")
#define CP_WAIT0()  asm volatile("cp.async.wait_group 0;" ::: "memory")

__device__ __forceinline__ void mma16816(float* d, const uint32_t* a, const uint32_t* b) {
    asm volatile("mma.sync.aligned.m16n8k16.row.col.f32.f16.f16.f32 "
        "{%0,%1,%2,%3}, {%4,%5,%6,%7}, {%8,%9}, {%0,%1,%2,%3};"
        : "+f"(d[0]), "+f"(d[1]), "+f"(d[2]), "+f"(d[3])
        : "r"(a[0]), "r"(a[1]), "r"(a[2]), "r"(a[3]), "r"(b[0]), "r"(b[1]));
}
__device__ __forceinline__ void ldm_a(uint32_t* a, uint32_t addr) {
    asm volatile("ldmatrix.sync.aligned.m8n8.x4.shared.b16 {%0,%1,%2,%3}, [%4];"
        : "=r"(a[0]), "=r"(a[1]), "=r"(a[2]), "=r"(a[3]) : "r"(addr));
}
__device__ __forceinline__ void ldm_b(uint32_t* b, uint32_t addr) {
    asm volatile("ldmatrix.sync.aligned.m8n8.x2.shared.b16 {%0,%1}, [%2];"
        : "=r"(b[0]), "=r"(b[1]) : "r"(addr));
}
__device__ __forceinline__ uint32_t aoff_b(int lane, int S) {
    return 2u * (uint32_t)((lane < 16) ? lane * S : (lane - 16) * S + 8);
}
__device__ __forceinline__ uint32_t boff_b(int lane, int S) {
    return 2u * (uint32_t)((lane & 7) * S + ((lane >> 3) & 1) * 8);
}
__device__ __forceinline__ void splitf(float x, __half& h, __half& l) {
    h = __float2half_rn(x);
    l = __float2half_rn(x - __half2float(h));
}
__device__ __forceinline__ uint32_t packh(__half a, __half b) {
    __half2 h2 = __halves2half2(a, b);
    return *reinterpret_cast<uint32_t*>(&h2);
}

// ---------------- split kernels ----------------
__global__ __launch_bounds__(256) void split_x_kernel(const float* __restrict__ X) {
    size_t i = ((size_t)blockIdx.x * 256 + threadIdx.x) * 4;
    float4 v = *(const float4*)(X + i);
    __half h0, l0, h1, l1, h2, l2, h3, l3;
    splitf(v.x, h0, l0); splitf(v.y, h1, l1); splitf(v.z, h2, l2); splitf(v.w, h3, l3);
    *(uint2*)&g_x[0][i] = make_uint2(packh(h0, h1), packh(h2, h3));
    *(uint2*)&g_x[1][i] = make_uint2(packh(l0, l1), packh(l2, l3));
}
__global__ __launch_bounds__(256) void split_w_kernel(
    const float* __restrict__ Wq, const float* __restrict__ Wk, const float* __restrict__ Wv) {
    size_t i = ((size_t)blockIdx.x * 256 + threadIdx.x) * 4;
    int z = (int)(i >> 16);
    size_t off = i & 65535;
    const float* W = (z == 0) ? Wq : ((z == 1) ? Wk : Wv);
    float4 v = *(const float4*)(W + off);
    __half h0, l0, h1, l1, h2, l2, h3, l3;
    splitf(v.x, h0, l0); splitf(v.y, h1, l1); splitf(v.z, h2, l2); splitf(v.w, h3, l3);
    *(uint2*)&g_w[0][z][off] = make_uint2(packh(h0, h1), packh(h2, h3));
    *(uint2*)&g_w[1][z][off] = make_uint2(packh(l0, l1), packh(l2, l3));
}

// ---------------- projection: Y = X @ W^T + b (fp16-split 3-MMA) ----------------
// z==2 (V) writes its output TRANSPOSED to g_vt via smem staging.
#define PJ_S 72
#define PJ_SMEM (4 * 18432)
__global__ __launch_bounds__(256, 2) void proj_kernel(
    const float* __restrict__ bq, const float* __restrict__ bk, const float* __restrict__ bv)
{
    extern __shared__ char sm[];
    __half* AH = (__half*)(sm);
    __half* AL = (__half*)(sm + 18432);
    __half* BH = (__half*)(sm + 36864);
    __half* BL = (__half*)(sm + 55296);

    const int tid = threadIdx.x, lane = tid & 31, w = tid >> 5;
    const int wy = w >> 1, wx = w & 1;
    const int rbase = blockIdx.x * 128, cbase = blockIdx.y * 128, z = blockIdx.z;
    const float* bias = (z == 0) ? bq : ((z == 1) ? bk : bv);

    const uint32_t sbp = smem_u32(sm);
    const uint32_t aoff = aoff_b(lane, PJ_S), boff = boff_b(lane, PJ_S);

    const uint4* xh4 = (const uint4*)(g_x[0]);
    const uint4* xl4 = (const uint4*)(g_x[1]);
    const uint4* wh4 = (const uint4*)(g_w[0][z]);
    const uint4* wl4 = (const uint4*)(g_w[1][z]);

    float acc[2][8][4];
#pragma unroll
    for (int mi = 0; mi < 2; mi++)
#pragma unroll
        for (int nj = 0; nj < 8; nj++)
#pragma unroll
            for (int c = 0; c < 4; c++) acc[mi][nj][c] = 0.f;

    for (int kc = 0; kc < 4; kc++) {
        __syncthreads();
#pragma unroll
        for (int it = 0; it < 4; it++) {
            int task = tid + 256 * it;           // 0..1023
            int r = task >> 3, c8 = task & 7;
            uint4 va = xh4[(size_t)(rbase + r) * 32 + kc * 8 + c8];
            uint4 vb = xl4[(size_t)(rbase + r) * 32 + kc * 8 + c8];
            uint4 vc = wh4[(size_t)(cbase + r) * 32 + kc * 8 + c8];
            uint4 vd = wl4[(size_t)(cbase + r) * 32 + kc * 8 + c8];
            *(uint4*)&AH[r * PJ_S + c8 * 8] = va;
            *(uint4*)&AL[r * PJ_S + c8 * 8] = vb;
            *(uint4*)&BH[r * PJ_S + c8 * 8] = vc;
            *(uint4*)&BL[r * PJ_S + c8 * 8] = vd;
        }
        __syncthreads();
#pragma unroll
        for (int ks = 0; ks < 4; ks++) {
            uint32_t ah[2][4], al[2][4];
#pragma unroll
            for (int mi = 0; mi < 2; mi++) {
                uint32_t ab = sbp + 2u * (uint32_t)((wy * 32 + mi * 16) * PJ_S + ks * 16) + aoff;
                ldm_a(ah[mi], ab);
                ldm_a(al[mi], ab + 18432);
            }
#pragma unroll
            for (int nj = 0; nj < 8; nj++) {
                uint32_t bh[2], bl[2];
                uint32_t bb = sbp + 36864 + 2u * (uint32_t)((wx * 64 + nj * 8) * PJ_S + ks * 16) + boff;
                ldm_b(bh, bb);
                ldm_b(bl, bb + 18432);
#pragma unroll
                for (int mi = 0; mi < 2; mi++) {
                    mma16816(acc[mi][nj], ah[mi], bh);
                    mma16816(acc[mi][nj], ah[mi], bl);
                    mma16816(acc[mi][nj], al[mi], bh);
                }
            }
        }
    }

    if (z < 2) {
        uint32_t* dh = (uint32_t*)((z == 0) ? g_q[0] : g_k[0]);
        uint32_t* dl = (uint32_t*)((z == 0) ? g_q[1] : g_k[1]);
#pragma unroll
        for (int mi = 0; mi < 2; mi++) {
            int rA = rbase + wy * 32 + mi * 16 + (lane >> 2);
#pragma unroll
            for (int nj = 0; nj < 8; nj++) {
                int col = cbase + wx * 64 + nj * 8 + 2 * (lane & 3);
                float b0 = __ldg(&bias[col]), b1 = __ldg(&bias[col + 1]);
                __half h0, l0, h1, l1;
                float y0 = acc[mi][nj][0] + b0, y1 = acc[mi][nj][1] + b1;
                splitf(y0, h0, l0); splitf(y1, h1, l1);
                dh[(size_t)rA * 128 + (col >> 1)] = packh(h0, h1);
                dl[(size_t)rA * 128 + (col >> 1)] = packh(l0, l1);
                float y2 = acc[mi][nj][2] + b0, y3 = acc[mi][nj][3] + b1;
                splitf(y2, h0, l0); splitf(y3, h1, l1);
                dh[(size_t)(rA + 8) * 128 + (col >> 1)] = packh(h0, h1);
                dl[(size_t)(rA + 8) * 128 + (col >> 1)] = packh(l0, l1);
            }
        }
    } else {
        // V: stage transposed tile [d 128][m 136] then write g_vt coalesced
        __syncthreads();
        __half* SH = (__half*)sm;              // 128*136*2 = 34816 B
        __half* SL = (__half*)(sm + 34816);
#pragma unroll
        for (int mi = 0; mi < 2; mi++) {
            int rowl = wy * 32 + mi * 16 + (lane >> 2);
#pragma unroll
            for (int nj = 0; nj < 8; nj++) {
                int coll = wx * 64 + nj * 8 + 2 * (lane & 3);
                float b0 = __ldg(&bias[cbase + coll]), b1 = __ldg(&bias[cbase + coll + 1]);
                __half h, l;
                splitf(acc[mi][nj][0] + b0, h, l);
                SH[coll * 136 + rowl] = h; SL[coll * 136 + rowl] = l;
                splitf(acc[mi][nj][1] + b1, h, l);
                SH[(coll + 1) * 136 + rowl] = h; SL[(coll + 1) * 136 + rowl] = l;
                splitf(acc[mi][nj][2] + b0, h, l);
                SH[coll * 136 + rowl + 8] = h; SL[coll * 136 + rowl + 8] = l;
                splitf(acc[mi][nj][3] + b1, h, l);
                SH[(coll + 1) * 136 + rowl + 8] = h; SL[(coll + 1) * 136 + rowl + 8] = l;
            }
        }
        __syncthreads();
        const int batch = rbase >> 10, mb = rbase & 1023;
        uint4* vth = (uint4*)(g_vt[0]);
        uint4* vtl = (uint4*)(g_vt[1]);
#pragma unroll
        for (int it = 0; it < 16; it++) {
            int task = tid + 256 * it;           // 0..4095
            int arr = task >> 11, idx = task & 2047;
            int d = idx >> 4, c8 = idx & 15;
            uint4 v = *(uint4*)&((arr ? SL : SH)[d * 136 + c8 * 8]);
            (arr ? vtl : vth)[(size_t)(batch * 256 + cbase + d) * 128 + (mb >> 3) + c8] = v;
        }
    }
}

// ---------------- attention: register-softmax flash, 128 q-rows/CTA ----------------
#define AT_QS 264
#define A_QH   0
#define A_QL   67584
#define A_BUF0 135168
#define BUFSZ  36864
#define AT_SMEM 208896

__device__ __forceinline__ void issue_stage(uint32_t sb, int st, int tid,
    const uint4* kh4, const uint4* kl4, const uint4* vh4, const uint4* vl4)
{
    if (st < 64) {
        int mt2 = st >> 3, ph2 = st & 7;
        uint32_t bo = sb + A_BUF0 + (uint32_t)(st & 1) * BUFSZ;
        int mbase = mt2 * 128;
        if (ph2 < 4) {
            int dc = ph2;                         // K: [m 128][64 d-chunk], stride 72
#pragma unroll
            for (int it = 0; it < 8; it++) {
                int task = tid + 256 * it;        // 0..2047
                int arr = task >> 10, idx = task & 1023;
                int r = idx >> 3, c8 = idx & 7;
                const uint4* src = (arr ? kl4 : kh4) + (size_t)(mbase + r) * 32 + dc * 8 + c8;
                cpa16(bo + (uint32_t)arr * 18432 + (uint32_t)(r * 72 + c8 * 8) * 2, src);
            }
        } else {
            int dc = ph2 - 4;                     // V^T: [d 64][m 128], stride 136
#pragma unroll
            for (int it = 0; it < 8; it++) {
                int task = tid + 256 * it;
                int arr = task >> 10, idx = task & 1023;
                int r = idx >> 4, c8 = idx & 15;
                const uint4* src = (arr ? vl4 : vh4) + (size_t)(dc * 64 + r) * 128 + (mbase >> 3) + c8;
                cpa16(bo + (uint32_t)arr * 18432 + (uint32_t)(r * 136 + c8 * 8) * 2, src);
            }
        }
    }
    CP_COMMIT();
}

__global__ __launch_bounds__(256, 1) void attn_kernel(float* __restrict__ out)
{
    extern __shared__ char sm[];
    const uint32_t sb = smem_u32(sm);
    __half* QH = (__half*)(sm + A_QH);
    __half* QL = (__half*)(sm + A_QL);

    const int b = blockIdx.y, qbase = blockIdx.x * 128;
    const int tid = threadIdx.x, lane = tid & 31, w = tid >> 5;

    const uint32_t aQ = sb + A_QH + 2u * (uint32_t)(w * 16 * AT_QS) + aoff_b(lane, AT_QS);
    const uint32_t bK = boff_b(lane, 72);
    const uint32_t bV = boff_b(lane, 136);

    const uint4* kh4 = (const uint4*)(g_k[0] + (size_t)b * SEQ * DIM);
    const uint4* kl4 = (const uint4*)(g_k[1] + (size_t)b * SEQ * DIM);
    const uint4* vh4 = (const uint4*)(g_vt[0] + (size_t)b * DIM * SEQ);
    const uint4* vl4 = (const uint4*)(g_vt[1] + (size_t)b * DIM * SEQ);

    issue_stage(sb, 0, tid, kh4, kl4, vh4, vl4);

    const uint4* qh4 = (const uint4*)(g_q[0] + (size_t)(b * SEQ + qbase) * DIM);
    const uint4* ql4 = (const uint4*)(g_q[1] + (size_t)(b * SEQ + qbase) * DIM);
#pragma unroll
    for (int it = 0; it < 32; it++) {
        int task = tid + 256 * it;               // 0..8191
        int arr = task >> 12, idx = task & 4095;
        int r = idx >> 5, c8 = idx & 31;
        uint4 v = (arr ? ql4 : qh4)[r * 32 + c8];
        *(uint4*)&((arr ? QL : QH)[r * AT_QS + c8 * 8]) = v;
    }

    float m0 = -1e30f, m1 = -1e30f, l0 = 0.f, l1 = 0.f;
    float o[32][4];
#pragma unroll
    for (int jn = 0; jn < 32; jn++)
#pragma unroll
        for (int c = 0; c < 4; c++) o[jn][c] = 0.f;

    int st = 0;
    for (int mt = 0; mt < 8; mt++) {
        float s[16][4];
#pragma unroll
        for (int nj = 0; nj < 16; nj++)
#pragma unroll
            for (int c = 0; c < 4; c++) s[nj][c] = 0.f;

        // ---- S = Q K^T: 4 K-chunk stages ----
        for (int dc = 0; dc < 4; dc++) {
            CP_WAIT0();
            __syncthreads();
            issue_stage(sb, st + 1, tid, kh4, kl4, vh4, vl4);
            const uint32_t kb = sb + A_BUF0 + (uint32_t)(st & 1) * BUFSZ;
#pragma unroll
            for (int ks = 0; ks < 4; ks++) {
                uint32_t ah[4], al[4];
                uint32_t ab = aQ + 2u * (uint32_t)(dc * 64 + ks * 16);
                ldm_a(ah, ab);
                ldm_a(al, ab + 67584);
#pragma unroll
                for (int nj = 0; nj < 16; nj++) {
                    uint32_t bh[2], bl[2];
                    uint32_t bb = kb + 2u * (uint32_t)(nj * 8 * 72 + ks * 16) + bK;
                    ldm_b(bh, bb);
                    ldm_b(bl, bb + 18432);
                    mma16816(s[nj], ah, bh);
                    mma16816(s[nj], ah, bl);
                    mma16816(s[nj], al, bh);
                }
            }
            st++;
        }

        // ---- register-only online softmax ----
        float mx0 = -1e30f, mx1 = -1e30f;
#pragma unroll
        for (int nj = 0; nj < 16; nj++) {
            mx0 = fmaxf(mx0, fmaxf(s[nj][0], s[nj][1]));
            mx1 = fmaxf(mx1, fmaxf(s[nj][2], s[nj][3]));
        }
        mx0 = fmaxf(mx0, __shfl_xor_sync(0xffffffffu, mx0, 1));
        mx0 = fmaxf(mx0, __shfl_xor_sync(0xffffffffu, mx0, 2));
        mx1 = fmaxf(mx1, __shfl_xor_sync(0xffffffffu, mx1, 1));
        mx1 = fmaxf(mx1, __shfl_xor_sync(0xffffffffu, mx1, 2));
        float mn0 = fmaxf(m0, mx0), mn1 = fmaxf(m1, mx1);
        float c0 = __expf(m0 - mn0), c1 = __expf(m1 - mn1);
        m0 = mn0; m1 = mn1;

        uint32_t ph[8][4], pl[8][4];
        float sum0 = 0.f, sum1 = 0.f;
#pragma unroll
        for (int ks = 0; ks < 8; ks++) {
            float e00 = __expf(s[2*ks][0] - m0),   e01 = __expf(s[2*ks][1] - m0);
            float e02 = __expf(s[2*ks][2] - m1),   e03 = __expf(s[2*ks][3] - m1);
            float e10 = __expf(s[2*ks+1][0] - m0), e11 = __expf(s[2*ks+1][1] - m0);
            float e12 = __expf(s[2*ks+1][2] - m1), e13 = __expf(s[2*ks+1][3] - m1);
            sum0 += e00 + e01 + e10 + e11;
            sum1 += e02 + e03 + e12 + e13;
            __half h0, lo0, h1, lo1;
            splitf(e00, h0, lo0); splitf(e01, h1, lo1);
            ph[ks][0] = packh(h0, h1); pl[ks][0] = packh(lo0, lo1);
            splitf(e02, h0, lo0); splitf(e03, h1, lo1);
            ph[ks][1] = packh(h0, h1); pl[ks][1] = packh(lo0, lo1);
            splitf(e10, h0, lo0); splitf(e11, h1, lo1);
            ph[ks][2] = packh(h0, h1); pl[ks][2] = packh(lo0, lo1);
            splitf(e12, h0, lo0); splitf(e13, h1, lo1);
            ph[ks][3] = packh(h0, h1); pl[ks][3] = packh(lo0, lo1);
        }
        sum0 += __shfl_xor_sync(0xffffffffu, sum0, 1);
        sum0 += __shfl_xor_sync(0xffffffffu, sum0, 2);
        sum1 += __shfl_xor_sync(0xffffffffu, sum1, 1);
        sum1 += __shfl_xor_sync(0xffffffffu, sum1, 2);
        l0 = l0 * c0 + sum0;
        l1 = l1 * c1 + sum1;

#pragma unroll
        for (int jn = 0; jn < 32; jn++) {
            o[jn][0] *= c0; o[jn][1] *= c0;
            o[jn][2] *= c1; o[jn][3] *= c1;
        }

        // ---- O += P @ V: 4 V-chunk stages (P in registers) ----
        for (int dc = 0; dc < 4; dc++) {
            CP_WAIT0();
            __syncthreads();
            issue_stage(sb, st + 1, tid, kh4, kl4, vh4, vl4);
            const uint32_t vb = sb + A_BUF0 + (uint32_t)(st & 1) * BUFSZ;
#pragma unroll
            for (int njl = 0; njl < 8; njl++) {
#pragma unroll
                for (int ks = 0; ks < 8; ks++) {
                    uint32_t bh[2], bl[2];
                    uint32_t bb = vb + 2u * (uint32_t)(njl * 8 * 136 + ks * 16) + bV;
                    ldm_b(bh, bb);
                    ldm_b(bl, bb + 18432);
                    mma16816(o[dc * 8 + njl], ph[ks], bh);
                    mma16816(o[dc * 8 + njl], ph[ks], bl);
                    mma16816(o[dc * 8 + njl], pl[ks], bh);
                }
            }
            st++;
        }
    }

    // ---- epilogue ----
    const float i0 = 1.0f / l0, i1 = 1.0f / l1;
    const int g0 = b * SEQ + qbase + w * 16 + (lane >> 2);
    const int g1 = g0 + 8;
#pragma unroll
    for (int jn = 0; jn < 32; jn++) {
        int d = jn * 8 + 2 * (lane & 3);
        *(float2*)&out[(size_t)g0 * DIM + d] = make_float2(o[jn][0] * i0, o[jn][1] * i0);
        *(float2*)&out[(size_t)g1 * DIM + d] = make_float2(o[jn][2] * i1, o[jn][3] * i1);
    }
}

// ---------------------------------------------------------------------------
extern "C" void kernel_launch(void* const* d_in, const int* in_sizes, int n_in,
                              void* d_out, int out_size)
{
    const float* traj = (const float*)d_in[0];
    const float* Wq = (const float*)d_in[1];
    const float* bq = (const float*)d_in[2];
    const float* Wk = (const float*)d_in[3];
    const float* bk = (const float*)d_in[4];
    const float* Wv = (const float*)d_in[5];
    const float* bv = (const float*)d_in[6];
    float* out = (float*)d_out;

    cudaFuncSetAttribute(proj_kernel, cudaFuncAttributeMaxDynamicSharedMemorySize, PJ_SMEM);
    cudaFuncSetAttribute(attn_kernel, cudaFuncAttributeMaxDynamicSharedMemorySize, AT_SMEM);

    split_x_kernel<<<8192, 256>>>(traj);
    split_w_kernel<<<192, 256>>>(Wq, Wk, Wv);
    proj_kernel<<<dim3(256, 2, 3), 256, PJ_SMEM>>>(bq, bk, bv);
    attn_kernel<<<dim3(8, 32), 256, AT_SMEM>>>(out);
}

// round 14
// speedup vs baseline: 3.9226x; 1.0796x over previous
#include <cuda_runtime.h>
#include <cuda_fp16.h>
#include <cstdint>

#define BATCH 32
#define SEQ   1024
#define DIM   256
#define NROWS (BATCH * SEQ)

// static scratch: fp16 hi/lo pairs
__device__ __align__(256) __half g_x [2][(size_t)NROWS * DIM];  // traj split
__device__ __align__(256) __half g_w [2][3][DIM * DIM];         // weights split
__device__ __align__(256) __half g_q [2][(size_t)NROWS * DIM];
__device__ __align__(256) __half g_k [2][(size_t)NROWS * DIM];
__device__ __align__(256) __half g_vt[2][(size_t)NROWS * DIM];  // [(b*256+d)*1024+m]

// ---------------- helpers ----------------
__device__ __forceinline__ uint32_t smem_u32(const void* p) {
    uint32_t a;
    asm("{ .reg .u64 t; cvta.to.shared.u64 t, %1; cvt.u32.u64 %0, t; }" : "=r"(a) : "l"(p));
    return a;
}
__device__ __forceinline__ void cpa16(uint32_t dst, const void* src) {
    asm volatile("cp.async.ca.shared.global [%0], [%1], 16;" :: "r"(dst), "l"(src));
}
#define CP_COMMIT() asm volatile("cp.async.commit_group;" ::: "memory")
#define CP_WAIT0()  asm volatile("cp.async.wait_group 0;" ::: "memory")

__device__ __forceinline__ void mma16816(float* d, const uint32_t* a, const uint32_t* b) {
    asm volatile("mma.sync.aligned.m16n8k16.row.col.f32.f16.f16.f32 "
        "{%0,%1,%2,%3}, {%4,%5,%6,%7}, {%8,%9}, {%0,%1,%2,%3};"
        : "+f"(d[0]), "+f"(d[1]), "+f"(d[2]), "+f"(d[3])
        : "r"(a[0]), "r"(a[1]), "r"(a[2]), "r"(a[3]), "r"(b[0]), "r"(b[1]));
}
__device__ __forceinline__ void ldm_a(uint32_t* a, uint32_t addr) {
    asm volatile("ldmatrix.sync.aligned.m8n8.x4.shared.b16 {%0,%1,%2,%3}, [%4];"
        : "=r"(a[0]), "=r"(a[1]), "=r"(a[2]), "=r"(a[3]) : "r"(addr));
}
__device__ __forceinline__ void ldm_b(uint32_t* b, uint32_t addr) {
    asm volatile("ldmatrix.sync.aligned.m8n8.x2.shared.b16 {%0,%1}, [%2];"
        : "=r"(b[0]), "=r"(b[1]) : "r"(addr));
}
__device__ __forceinline__ uint32_t aoff_b(int lane, int S) {
    return 2u * (uint32_t)((lane < 16) ? lane * S : (lane - 16) * S + 8);
}
__device__ __forceinline__ uint32_t boff_b(int lane, int S) {
    return 2u * (uint32_t)((lane & 7) * S + ((lane >> 3) & 1) * 8);
}
__device__ __forceinline__ void splitf(float x, __half& h, __half& l) {
    h = __float2half_rn(x);
    l = __float2half_rn(x - __half2float(h));
}
__device__ __forceinline__ uint32_t packh(__half a, __half b) {
    __half2 h2 = __halves2half2(a, b);
    return *reinterpret_cast<uint32_t*>(&h2);
}

// ---------------- split kernels ----------------
__global__ __launch_bounds__(256) void split_x_kernel(const float* __restrict__ X) {
    size_t i = ((size_t)blockIdx.x * 256 + threadIdx.x) * 4;
    float4 v = *(const float4*)(X + i);
    __half h0, l0, h1, l1, h2, l2, h3, l3;
    splitf(v.x, h0, l0); splitf(v.y, h1, l1); splitf(v.z, h2, l2); splitf(v.w, h3, l3);
    *(uint2*)&g_x[0][i] = make_uint2(packh(h0, h1), packh(h2, h3));
    *(uint2*)&g_x[1][i] = make_uint2(packh(l0, l1), packh(l2, l3));
}
__global__ __launch_bounds__(256) void split_w_kernel(
    const float* __restrict__ Wq, const float* __restrict__ Wk, const float* __restrict__ Wv) {
    size_t i = ((size_t)blockIdx.x * 256 + threadIdx.x) * 4;
    int z = (int)(i >> 16);
    size_t off = i & 65535;
    const float* W = (z == 0) ? Wq : ((z == 1) ? Wk : Wv);
    float4 v = *(const float4*)(W + off);
    __half h0, l0, h1, l1, h2, l2, h3, l3;
    splitf(v.x, h0, l0); splitf(v.y, h1, l1); splitf(v.z, h2, l2); splitf(v.w, h3, l3);
    *(uint2*)&g_w[0][z][off] = make_uint2(packh(h0, h1), packh(h2, h3));
    *(uint2*)&g_w[1][z][off] = make_uint2(packh(l0, l1), packh(l2, l3));
}

// ---------------- projection: Y = X @ W^T + b (fp16-split 3-MMA) ----------------
// z==2 (V) writes its output TRANSPOSED to g_vt via smem staging.
#define PJ_S 72
#define PJ_SMEM (4 * 18432)
__global__ __launch_bounds__(256, 2) void proj_kernel(
    const float* __restrict__ bq, const float* __restrict__ bk, const float* __restrict__ bv)
{
    extern __shared__ char sm[];
    __half* AH = (__half*)(sm);
    __half* AL = (__half*)(sm + 18432);
    __half* BH = (__half*)(sm + 36864);
    __half* BL = (__half*)(sm + 55296);

    const int tid = threadIdx.x, lane = tid & 31, w = tid >> 5;
    const int wy = w >> 1, wx = w & 1;
    const int rbase = blockIdx.x * 128, cbase = blockIdx.y * 128, z = blockIdx.z;
    const float* bias = (z == 0) ? bq : ((z == 1) ? bk : bv);

    const uint32_t sbp = smem_u32(sm);
    const uint32_t aoff = aoff_b(lane, PJ_S), boff = boff_b(lane, PJ_S);

    const uint4* xh4 = (const uint4*)(g_x[0]);
    const uint4* xl4 = (const uint4*)(g_x[1]);
    const uint4* wh4 = (const uint4*)(g_w[0][z]);
    const uint4* wl4 = (const uint4*)(g_w[1][z]);

    float acc[2][8][4];
#pragma unroll
    for (int mi = 0; mi < 2; mi++)
#pragma unroll
        for (int nj = 0; nj < 8; nj++)
#pragma unroll
            for (int c = 0; c < 4; c++) acc[mi][nj][c] = 0.f;

    for (int kc = 0; kc < 4; kc++) {
        __syncthreads();
#pragma unroll
        for (int it = 0; it < 4; it++) {
            int task = tid + 256 * it;           // 0..1023
            int r = task >> 3, c8 = task & 7;
            uint4 va = xh4[(size_t)(rbase + r) * 32 + kc * 8 + c8];
            uint4 vb = xl4[(size_t)(rbase + r) * 32 + kc * 8 + c8];
            uint4 vc = wh4[(size_t)(cbase + r) * 32 + kc * 8 + c8];
            uint4 vd = wl4[(size_t)(cbase + r) * 32 + kc * 8 + c8];
            *(uint4*)&AH[r * PJ_S + c8 * 8] = va;
            *(uint4*)&AL[r * PJ_S + c8 * 8] = vb;
            *(uint4*)&BH[r * PJ_S + c8 * 8] = vc;
            *(uint4*)&BL[r * PJ_S + c8 * 8] = vd;
        }
        __syncthreads();
#pragma unroll
        for (int ks = 0; ks < 4; ks++) {
            uint32_t ah[2][4], al[2][4];
#pragma unroll
            for (int mi = 0; mi < 2; mi++) {
                uint32_t ab = sbp + 2u * (uint32_t)((wy * 32 + mi * 16) * PJ_S + ks * 16) + aoff;
                ldm_a(ah[mi], ab);
                ldm_a(al[mi], ab + 18432);
            }
#pragma unroll
            for (int nj = 0; nj < 8; nj++) {
                uint32_t bh[2], bl[2];
                uint32_t bb = sbp + 36864 + 2u * (uint32_t)((wx * 64 + nj * 8) * PJ_S + ks * 16) + boff;
                ldm_b(bh, bb);
                ldm_b(bl, bb + 18432);
#pragma unroll
                for (int mi = 0; mi < 2; mi++) {
                    mma16816(acc[mi][nj], ah[mi], bh);
                    mma16816(acc[mi][nj], ah[mi], bl);
                    mma16816(acc[mi][nj], al[mi], bh);
                }
            }
        }
    }

    if (z < 2) {
        uint32_t* dh = (uint32_t*)((z == 0) ? g_q[0] : g_k[0]);
        uint32_t* dl = (uint32_t*)((z == 0) ? g_q[1] : g_k[1]);
#pragma unroll
        for (int mi = 0; mi < 2; mi++) {
            int rA = rbase + wy * 32 + mi * 16 + (lane >> 2);
#pragma unroll
            for (int nj = 0; nj < 8; nj++) {
                int col = cbase + wx * 64 + nj * 8 + 2 * (lane & 3);
                float b0 = __ldg(&bias[col]), b1 = __ldg(&bias[col + 1]);
                __half h0, l0, h1, l1;
                float y0 = acc[mi][nj][0] + b0, y1 = acc[mi][nj][1] + b1;
                splitf(y0, h0, l0); splitf(y1, h1, l1);
                dh[(size_t)rA * 128 + (col >> 1)] = packh(h0, h1);
                dl[(size_t)rA * 128 + (col >> 1)] = packh(l0, l1);
                float y2 = acc[mi][nj][2] + b0, y3 = acc[mi][nj][3] + b1;
                splitf(y2, h0, l0); splitf(y3, h1, l1);
                dh[(size_t)(rA + 8) * 128 + (col >> 1)] = packh(h0, h1);
                dl[(size_t)(rA + 8) * 128 + (col >> 1)] = packh(l0, l1);
            }
        }
    } else {
        // V: stage transposed tile [d 128][m 136] then write g_vt coalesced
        __syncthreads();
        __half* SH = (__half*)sm;              // 128*136*2 = 34816 B
        __half* SL = (__half*)(sm + 34816);
#pragma unroll
        for (int mi = 0; mi < 2; mi++) {
            int rowl = wy * 32 + mi * 16 + (lane >> 2);
#pragma unroll
            for (int nj = 0; nj < 8; nj++) {
                int coll = wx * 64 + nj * 8 + 2 * (lane & 3);
                float b0 = __ldg(&bias[cbase + coll]), b1 = __ldg(&bias[cbase + coll + 1]);
                __half h, l;
                splitf(acc[mi][nj][0] + b0, h, l);
                SH[coll * 136 + rowl] = h; SL[coll * 136 + rowl] = l;
                splitf(acc[mi][nj][1] + b1, h, l);
                SH[(coll + 1) * 136 + rowl] = h; SL[(coll + 1) * 136 + rowl] = l;
                splitf(acc[mi][nj][2] + b0, h, l);
                SH[coll * 136 + rowl + 8] = h; SL[coll * 136 + rowl + 8] = l;
                splitf(acc[mi][nj][3] + b1, h, l);
                SH[(coll + 1) * 136 + rowl + 8] = h; SL[(coll + 1) * 136 + rowl + 8] = l;
            }
        }
        __syncthreads();
        const int batch = rbase >> 10, mb = rbase & 1023;
        uint4* vth = (uint4*)(g_vt[0]);
        uint4* vtl = (uint4*)(g_vt[1]);
#pragma unroll
        for (int it = 0; it < 16; it++) {
            int task = tid + 256 * it;           // 0..4095
            int arr = task >> 11, idx = task & 2047;
            int d = idx >> 4, c8 = idx & 15;
            uint4 v = *(uint4*)&((arr ? SL : SH)[d * 136 + c8 * 8]);
            (arr ? vtl : vth)[(size_t)(batch * 256 + cbase + d) * 128 + (mb >> 3) + c8] = v;
        }
    }
}

// ---------------- attention: register-softmax flash, 128 q-rows/CTA ----------------
#define AT_QS 264
#define A_QH   0
#define A_QL   67584
#define A_BUF0 135168
#define BUFSZ  36864
#define AT_SMEM 208896

__device__ __forceinline__ void issue_stage(uint32_t sb, int st, int tid,
    const uint4* kh4, const uint4* kl4, const uint4* vh4, const uint4* vl4)
{
    if (st < 64) {
        int mt2 = st >> 3, ph2 = st & 7;
        uint32_t bo = sb + A_BUF0 + (uint32_t)(st & 1) * BUFSZ;
        int mbase = mt2 * 128;
        if (ph2 < 4) {
            int dc = ph2;                         // K: [m 128][64 d-chunk], stride 72
#pragma unroll
            for (int it = 0; it < 8; it++) {
                int task = tid + 256 * it;        // 0..2047
                int arr = task >> 10, idx = task & 1023;
                int r = idx >> 3, c8 = idx & 7;
                const uint4* src = (arr ? kl4 : kh4) + (size_t)(mbase + r) * 32 + dc * 8 + c8;
                cpa16(bo + (uint32_t)arr * 18432 + (uint32_t)(r * 72 + c8 * 8) * 2, src);
            }
        } else {
            int dc = ph2 - 4;                     // V^T: [d 64][m 128], stride 136
#pragma unroll
            for (int it = 0; it < 8; it++) {
                int task = tid + 256 * it;
                int arr = task >> 10, idx = task & 1023;
                int r = idx >> 4, c8 = idx & 15;
                const uint4* src = (arr ? vl4 : vh4) + (size_t)(dc * 64 + r) * 128 + (mbase >> 3) + c8;
                cpa16(bo + (uint32_t)arr * 18432 + (uint32_t)(r * 136 + c8 * 8) * 2, src);
            }
        }
    }
    CP_COMMIT();
}

__global__ __launch_bounds__(256, 1) void attn_kernel(float* __restrict__ out)
{
    extern __shared__ char sm[];
    const uint32_t sb = smem_u32(sm);
    __half* QH = (__half*)(sm + A_QH);
    __half* QL = (__half*)(sm + A_QL);

    const int b = blockIdx.y, qbase = blockIdx.x * 128;
    const int tid = threadIdx.x, lane = tid & 31, w = tid >> 5;

    const uint32_t aQ = sb + A_QH + 2u * (uint32_t)(w * 16 * AT_QS) + aoff_b(lane, AT_QS);
    const uint32_t bK = boff_b(lane, 72);
    const uint32_t bV = boff_b(lane, 136);

    const uint4* kh4 = (const uint4*)(g_k[0] + (size_t)b * SEQ * DIM);
    const uint4* kl4 = (const uint4*)(g_k[1] + (size_t)b * SEQ * DIM);
    const uint4* vh4 = (const uint4*)(g_vt[0] + (size_t)b * DIM * SEQ);
    const uint4* vl4 = (const uint4*)(g_vt[1] + (size_t)b * DIM * SEQ);

    issue_stage(sb, 0, tid, kh4, kl4, vh4, vl4);

    const uint4* qh4 = (const uint4*)(g_q[0] + (size_t)(b * SEQ + qbase) * DIM);
    const uint4* ql4 = (const uint4*)(g_q[1] + (size_t)(b * SEQ + qbase) * DIM);
#pragma unroll
    for (int it = 0; it < 32; it++) {
        int task = tid + 256 * it;               // 0..8191
        int arr = task >> 12, idx = task & 4095;
        int r = idx >> 5, c8 = idx & 31;
        uint4 v = (arr ? ql4 : qh4)[r * 32 + c8];
        *(uint4*)&((arr ? QL : QH)[r * AT_QS + c8 * 8]) = v;
    }

    float m0 = -1e30f, m1 = -1e30f, l0 = 0.f, l1 = 0.f;
    float o[32][4];
#pragma unroll
    for (int jn = 0; jn < 32; jn++)
#pragma unroll
        for (int c = 0; c < 4; c++) o[jn][c] = 0.f;

    int st = 0;
    for (int mt = 0; mt < 8; mt++) {
        float s[16][4];
#pragma unroll
        for (int nj = 0; nj < 16; nj++)
#pragma unroll
            for (int c = 0; c < 4; c++) s[nj][c] = 0.f;

        // ---- S = Q K^T: 4 K-chunk stages ----
        for (int dc = 0; dc < 4; dc++) {
            CP_WAIT0();
            __syncthreads();
            issue_stage(sb, st + 1, tid, kh4, kl4, vh4, vl4);
            const uint32_t kb = sb + A_BUF0 + (uint32_t)(st & 1) * BUFSZ;
#pragma unroll
            for (int ks = 0; ks < 4; ks++) {
                uint32_t ah[4], al[4];
                uint32_t ab = aQ + 2u * (uint32_t)(dc * 64 + ks * 16);
                ldm_a(ah, ab);
                ldm_a(al, ab + 67584);
#pragma unroll
                for (int nj = 0; nj < 16; nj++) {
                    uint32_t bh[2], bl[2];
                    uint32_t bb = kb + 2u * (uint32_t)(nj * 8 * 72 + ks * 16) + bK;
                    ldm_b(bh, bb);
                    ldm_b(bl, bb + 18432);
                    mma16816(s[nj], ah, bh);
                    mma16816(s[nj], ah, bl);
                    mma16816(s[nj], al, bh);
                }
            }
            st++;
        }

        // ---- register-only online softmax; P -> fp16 (hi only) ----
        float mx0 = -1e30f, mx1 = -1e30f;
#pragma unroll
        for (int nj = 0; nj < 16; nj++) {
            mx0 = fmaxf(mx0, fmaxf(s[nj][0], s[nj][1]));
            mx1 = fmaxf(mx1, fmaxf(s[nj][2], s[nj][3]));
        }
        mx0 = fmaxf(mx0, __shfl_xor_sync(0xffffffffu, mx0, 1));
        mx0 = fmaxf(mx0, __shfl_xor_sync(0xffffffffu, mx0, 2));
        mx1 = fmaxf(mx1, __shfl_xor_sync(0xffffffffu, mx1, 1));
        mx1 = fmaxf(mx1, __shfl_xor_sync(0xffffffffu, mx1, 2));
        float mn0 = fmaxf(m0, mx0), mn1 = fmaxf(m1, mx1);
        float c0 = __expf(m0 - mn0), c1 = __expf(m1 - mn1);
        m0 = mn0; m1 = mn1;

        uint32_t ph[8][4];
        float sum0 = 0.f, sum1 = 0.f;
#pragma unroll
        for (int ks = 0; ks < 8; ks++) {
            float e00 = __expf(s[2*ks][0] - m0),   e01 = __expf(s[2*ks][1] - m0);
            float e02 = __expf(s[2*ks][2] - m1),   e03 = __expf(s[2*ks][3] - m1);
            float e10 = __expf(s[2*ks+1][0] - m0), e11 = __expf(s[2*ks+1][1] - m0);
            float e12 = __expf(s[2*ks+1][2] - m1), e13 = __expf(s[2*ks+1][3] - m1);
            sum0 += e00 + e01 + e10 + e11;
            sum1 += e02 + e03 + e12 + e13;
            ph[ks][0] = packh(__float2half_rn(e00), __float2half_rn(e01));
            ph[ks][1] = packh(__float2half_rn(e02), __float2half_rn(e03));
            ph[ks][2] = packh(__float2half_rn(e10), __float2half_rn(e11));
            ph[ks][3] = packh(__float2half_rn(e12), __float2half_rn(e13));
        }
        sum0 += __shfl_xor_sync(0xffffffffu, sum0, 1);
        sum0 += __shfl_xor_sync(0xffffffffu, sum0, 2);
        sum1 += __shfl_xor_sync(0xffffffffu, sum1, 1);
        sum1 += __shfl_xor_sync(0xffffffffu, sum1, 2);
        l0 = l0 * c0 + sum0;
        l1 = l1 * c1 + sum1;

#pragma unroll
        for (int jn = 0; jn < 32; jn++) {
            o[jn][0] *= c0; o[jn][1] *= c0;
            o[jn][2] *= c1; o[jn][3] *= c1;
        }

        // ---- O += P @ V: 4 V-chunk stages (P fp16 in registers, 2-MMA) ----
        for (int dc = 0; dc < 4; dc++) {
            CP_WAIT0();
            __syncthreads();
            issue_stage(sb, st + 1, tid, kh4, kl4, vh4, vl4);
            const uint32_t vb = sb + A_BUF0 + (uint32_t)(st & 1) * BUFSZ;
#pragma unroll
            for (int njl = 0; njl < 8; njl++) {
#pragma unroll
                for (int ks = 0; ks < 8; ks++) {
                    uint32_t bh[2], bl[2];
                    uint32_t bb = vb + 2u * (uint32_t)(njl * 8 * 136 + ks * 16) + bV;
                    ldm_b(bh, bb);
                    ldm_b(bl, bb + 18432);
                    mma16816(o[dc * 8 + njl], ph[ks], bh);
                    mma16816(o[dc * 8 + njl], ph[ks], bl);
                }
            }
            st++;
        }
    }

    // ---- epilogue ----
    const float i0 = 1.0f / l0, i1 = 1.0f / l1;
    const int g0 = b * SEQ + qbase + w * 16 + (lane >> 2);
    const int g1 = g0 + 8;
#pragma unroll
    for (int jn = 0; jn < 32; jn++) {
        int d = jn * 8 + 2 * (lane & 3);
        *(float2*)&out[(size_t)g0 * DIM + d] = make_float2(o[jn][0] * i0, o[jn][1] * i0);
        *(float2*)&out[(size_t)g1 * DIM + d] = make_float2(o[jn][2] * i1, o[jn][3] * i1);
    }
}

// ---------------------------------------------------------------------------
extern "C" void kernel_launch(void* const* d_in, const int* in_sizes, int n_in,
                              void* d_out, int out_size)
{
    const float* traj = (const float*)d_in[0];
    const float* Wq = (const float*)d_in[1];
    const float* bq = (const float*)d_in[2];
    const float* Wk = (const float*)d_in[3];
    const float* bk = (const float*)d_in[4];
    const float* Wv = (const float*)d_in[5];
    const float* bv = (const float*)d_in[6];
    float* out = (float*)d_out;

    cudaFuncSetAttribute(proj_kernel, cudaFuncAttributeMaxDynamicSharedMemorySize, PJ_SMEM);
    cudaFuncSetAttribute(attn_kernel, cudaFuncAttributeMaxDynamicSharedMemorySize, AT_SMEM);

    split_x_kernel<<<8192, 256>>>(traj);
    split_w_kernel<<<192, 256>>>(Wq, Wk, Wv);
    proj_kernel<<<dim3(256, 2, 3), 256, PJ_SMEM>>>(bq, bk, bv);
    attn_kernel<<<dim3(8, 32), 256, AT_SMEM>>>(out);
}

// round 15
// speedup vs baseline: 4.2047x; 1.0719x over previous
#include <cuda_runtime.h>
#include <cuda_fp16.h>
#include <cstdint>

#define BATCH 32
#define SEQ   1024
#define DIM   256
#define NROWS (BATCH * SEQ)

// static scratch: fp16 hi/lo pairs
__device__ __align__(256) __half g_x [2][(size_t)NROWS * DIM];  // traj split
__device__ __align__(256) __half g_w [2][3][DIM * DIM];         // weights split
__device__ __align__(256) __half g_q [2][(size_t)NROWS * DIM];
__device__ __align__(256) __half g_k [2][(size_t)NROWS * DIM];
__device__ __align__(256) __half g_vt[2][(size_t)NROWS * DIM];  // [(b*256+d)*1024+m]

// ---------------- helpers ----------------
__device__ __forceinline__ uint32_t smem_u32(const void* p) {
    uint32_t a;
    asm("{ .reg .u64 t; cvta.to.shared.u64 t, %1; cvt.u32.u64 %0, t; }" : "=r"(a) : "l"(p));
    return a;
}
__device__ __forceinline__ void cpa16(uint32_t dst, const void* src) {
    asm volatile("cp.async.ca.shared.global [%0], [%1], 16;" :: "r"(dst), "l"(src));
}
#define CP_COMMIT() asm volatile("cp.async.commit_group;" ::: "memory")
#define CP_WAIT0()  asm volatile("cp.async.wait_group 0;" ::: "memory")

__device__ __forceinline__ void mma16816(float* d, const uint32_t* a, const uint32_t* b) {
    asm volatile("mma.sync.aligned.m16n8k16.row.col.f32.f16.f16.f32 "
        "{%0,%1,%2,%3}, {%4,%5,%6,%7}, {%8,%9}, {%0,%1,%2,%3};"
        : "+f"(d[0]), "+f"(d[1]), "+f"(d[2]), "+f"(d[3])
        : "r"(a[0]), "r"(a[1]), "r"(a[2]), "r"(a[3]), "r"(b[0]), "r"(b[1]));
}
__device__ __forceinline__ void ldm_a(uint32_t* a, uint32_t addr) {
    asm volatile("ldmatrix.sync.aligned.m8n8.x4.shared.b16 {%0,%1,%2,%3}, [%4];"
        : "=r"(a[0]), "=r"(a[1]), "=r"(a[2]), "=r"(a[3]) : "r"(addr));
}
__device__ __forceinline__ void ldm_b(uint32_t* b, uint32_t addr) {
    asm volatile("ldmatrix.sync.aligned.m8n8.x2.shared.b16 {%0,%1}, [%2];"
        : "=r"(b[0]), "=r"(b[1]) : "r"(addr));
}
__device__ __forceinline__ uint32_t aoff_b(int lane, int S) {
    return 2u * (uint32_t)((lane < 16) ? lane * S : (lane - 16) * S + 8);
}
__device__ __forceinline__ uint32_t boff_b(int lane, int S) {
    return 2u * (uint32_t)((lane & 7) * S + ((lane >> 3) & 1) * 8);
}
__device__ __forceinline__ void splitf(float x, __half& h, __half& l) {
    h = __float2half_rn(x);
    l = __float2half_rn(x - __half2float(h));
}
__device__ __forceinline__ uint32_t packh(__half a, __half b) {
    __half2 h2 = __halves2half2(a, b);
    return *reinterpret_cast<uint32_t*>(&h2);
}

// ---------------- split kernels ----------------
__global__ __launch_bounds__(256) void split_x_kernel(const float* __restrict__ X) {
    size_t i = ((size_t)blockIdx.x * 256 + threadIdx.x) * 4;
    float4 v = *(const float4*)(X + i);
    __half h0, l0, h1, l1, h2, l2, h3, l3;
    splitf(v.x, h0, l0); splitf(v.y, h1, l1); splitf(v.z, h2, l2); splitf(v.w, h3, l3);
    *(uint2*)&g_x[0][i] = make_uint2(packh(h0, h1), packh(h2, h3));
    *(uint2*)&g_x[1][i] = make_uint2(packh(l0, l1), packh(l2, l3));
}
__global__ __launch_bounds__(256) void split_w_kernel(
    const float* __restrict__ Wq, const float* __restrict__ Wk, const float* __restrict__ Wv) {
    size_t i = ((size_t)blockIdx.x * 256 + threadIdx.x) * 4;
    int z = (int)(i >> 16);
    size_t off = i & 65535;
    const float* W = (z == 0) ? Wq : ((z == 1) ? Wk : Wv);
    float4 v = *(const float4*)(W + off);
    __half h0, l0, h1, l1, h2, l2, h3, l3;
    splitf(v.x, h0, l0); splitf(v.y, h1, l1); splitf(v.z, h2, l2); splitf(v.w, h3, l3);
    *(uint2*)&g_w[0][z][off] = make_uint2(packh(h0, h1), packh(h2, h3));
    *(uint2*)&g_w[1][z][off] = make_uint2(packh(l0, l1), packh(l2, l3));
}

// ---------------- projection: Y = X @ W^T + b (fp16-split 3-MMA) ----------------
// z==2 (V) writes its output TRANSPOSED to g_vt via smem staging.
#define PJ_S 72
#define PJ_SMEM (4 * 18432)
__global__ __launch_bounds__(256, 2) void proj_kernel(
    const float* __restrict__ bq, const float* __restrict__ bk, const float* __restrict__ bv)
{
    extern __shared__ char sm[];
    __half* AH = (__half*)(sm);
    __half* AL = (__half*)(sm + 18432);
    __half* BH = (__half*)(sm + 36864);
    __half* BL = (__half*)(sm + 55296);

    const int tid = threadIdx.x, lane = tid & 31, w = tid >> 5;
    const int wy = w >> 1, wx = w & 1;
    const int rbase = blockIdx.x * 128, cbase = blockIdx.y * 128, z = blockIdx.z;
    const float* bias = (z == 0) ? bq : ((z == 1) ? bk : bv);

    const uint32_t sbp = smem_u32(sm);
    const uint32_t aoff = aoff_b(lane, PJ_S), boff = boff_b(lane, PJ_S);

    const uint4* xh4 = (const uint4*)(g_x[0]);
    const uint4* xl4 = (const uint4*)(g_x[1]);
    const uint4* wh4 = (const uint4*)(g_w[0][z]);
    const uint4* wl4 = (const uint4*)(g_w[1][z]);

    float acc[2][8][4];
#pragma unroll
    for (int mi = 0; mi < 2; mi++)
#pragma unroll
        for (int nj = 0; nj < 8; nj++)
#pragma unroll
            for (int c = 0; c < 4; c++) acc[mi][nj][c] = 0.f;

    for (int kc = 0; kc < 4; kc++) {
        __syncthreads();
#pragma unroll
        for (int it = 0; it < 4; it++) {
            int task = tid + 256 * it;           // 0..1023
            int r = task >> 3, c8 = task & 7;
            uint4 va = xh4[(size_t)(rbase + r) * 32 + kc * 8 + c8];
            uint4 vb = xl4[(size_t)(rbase + r) * 32 + kc * 8 + c8];
            uint4 vc = wh4[(size_t)(cbase + r) * 32 + kc * 8 + c8];
            uint4 vd = wl4[(size_t)(cbase + r) * 32 + kc * 8 + c8];
            *(uint4*)&AH[r * PJ_S + c8 * 8] = va;
            *(uint4*)&AL[r * PJ_S + c8 * 8] = vb;
            *(uint4*)&BH[r * PJ_S + c8 * 8] = vc;
            *(uint4*)&BL[r * PJ_S + c8 * 8] = vd;
        }
        __syncthreads();
#pragma unroll
        for (int ks = 0; ks < 4; ks++) {
            uint32_t ah[2][4], al[2][4];
#pragma unroll
            for (int mi = 0; mi < 2; mi++) {
                uint32_t ab = sbp + 2u * (uint32_t)((wy * 32 + mi * 16) * PJ_S + ks * 16) + aoff;
                ldm_a(ah[mi], ab);
                ldm_a(al[mi], ab + 18432);
            }
#pragma unroll
            for (int nj = 0; nj < 8; nj++) {
                uint32_t bh[2], bl[2];
                uint32_t bb = sbp + 36864 + 2u * (uint32_t)((wx * 64 + nj * 8) * PJ_S + ks * 16) + boff;
                ldm_b(bh, bb);
                ldm_b(bl, bb + 18432);
#pragma unroll
                for (int mi = 0; mi < 2; mi++) {
                    mma16816(acc[mi][nj], ah[mi], bh);
                    mma16816(acc[mi][nj], ah[mi], bl);
                    mma16816(acc[mi][nj], al[mi], bh);
                }
            }
        }
    }

    if (z < 2) {
        uint32_t* dh = (uint32_t*)((z == 0) ? g_q[0] : g_k[0]);
        uint32_t* dl = (uint32_t*)((z == 0) ? g_q[1] : g_k[1]);
#pragma unroll
        for (int mi = 0; mi < 2; mi++) {
            int rA = rbase + wy * 32 + mi * 16 + (lane >> 2);
#pragma unroll
            for (int nj = 0; nj < 8; nj++) {
                int col = cbase + wx * 64 + nj * 8 + 2 * (lane & 3);
                float b0 = __ldg(&bias[col]), b1 = __ldg(&bias[col + 1]);
                __half h0, l0, h1, l1;
                float y0 = acc[mi][nj][0] + b0, y1 = acc[mi][nj][1] + b1;
                splitf(y0, h0, l0); splitf(y1, h1, l1);
                dh[(size_t)rA * 128 + (col >> 1)] = packh(h0, h1);
                dl[(size_t)rA * 128 + (col >> 1)] = packh(l0, l1);
                float y2 = acc[mi][nj][2] + b0, y3 = acc[mi][nj][3] + b1;
                splitf(y2, h0, l0); splitf(y3, h1, l1);
                dh[(size_t)(rA + 8) * 128 + (col >> 1)] = packh(h0, h1);
                dl[(size_t)(rA + 8) * 128 + (col >> 1)] = packh(l0, l1);
            }
        }
    } else {
        // V: stage transposed tile [d 128][m 136] then write g_vt coalesced
        __syncthreads();
        __half* SH = (__half*)sm;              // 128*136*2 = 34816 B
        __half* SL = (__half*)(sm + 34816);
#pragma unroll
        for (int mi = 0; mi < 2; mi++) {
            int rowl = wy * 32 + mi * 16 + (lane >> 2);
#pragma unroll
            for (int nj = 0; nj < 8; nj++) {
                int coll = wx * 64 + nj * 8 + 2 * (lane & 3);
                float b0 = __ldg(&bias[cbase + coll]), b1 = __ldg(&bias[cbase + coll + 1]);
                __half h, l;
                splitf(acc[mi][nj][0] + b0, h, l);
                SH[coll * 136 + rowl] = h; SL[coll * 136 + rowl] = l;
                splitf(acc[mi][nj][1] + b1, h, l);
                SH[(coll + 1) * 136 + rowl] = h; SL[(coll + 1) * 136 + rowl] = l;
                splitf(acc[mi][nj][2] + b0, h, l);
                SH[coll * 136 + rowl + 8] = h; SL[coll * 136 + rowl + 8] = l;
                splitf(acc[mi][nj][3] + b1, h, l);
                SH[(coll + 1) * 136 + rowl + 8] = h; SL[(coll + 1) * 136 + rowl + 8] = l;
            }
        }
        __syncthreads();
        const int batch = rbase >> 10, mb = rbase & 1023;
        uint4* vth = (uint4*)(g_vt[0]);
        uint4* vtl = (uint4*)(g_vt[1]);
#pragma unroll
        for (int it = 0; it < 16; it++) {
            int task = tid + 256 * it;           // 0..4095
            int arr = task >> 11, idx = task & 2047;
            int d = idx >> 4, c8 = idx & 15;
            uint4 v = *(uint4*)&((arr ? SL : SH)[d * 136 + c8 * 8]);
            (arr ? vtl : vth)[(size_t)(batch * 256 + cbase + d) * 128 + (mb >> 3) + c8] = v;
        }
    }
}

// ---------------- attention: register-softmax flash, 128 q-rows/CTA, kv-tile 64 ----------------
#define AT_QS 264
#define A_QH   0
#define A_QL   67584
#define A_BUF0 135168
#define BUFSZ  18432
#define AT_SMEM 172032

__device__ __forceinline__ void issue_stage(uint32_t sb, int st, int tid,
    const uint4* kh4, const uint4* kl4, const uint4* vh4, const uint4* vl4)
{
    if (st < 128) {
        int mt2 = st >> 3, ph2 = st & 7;
        uint32_t bo = sb + A_BUF0 + (uint32_t)(st & 1) * BUFSZ;
        int mbase = mt2 * 64;
        if (ph2 < 4) {
            int dc = ph2;                         // K: [m 64][64 d-chunk], stride 72
#pragma unroll
            for (int it = 0; it < 4; it++) {
                int task = tid + 256 * it;        // 0..1023
                int arr = task >> 9, idx = task & 511;
                int r = idx >> 3, c8 = idx & 7;
                const uint4* src = (arr ? kl4 : kh4) + (size_t)(mbase + r) * 32 + dc * 8 + c8;
                cpa16(bo + (uint32_t)arr * 9216 + (uint32_t)(r * 72 + c8 * 8) * 2, src);
            }
        } else {
            int dc = ph2 - 4;                     // V^T: [d 64][m 64], stride 72
#pragma unroll
            for (int it = 0; it < 4; it++) {
                int task = tid + 256 * it;
                int arr = task >> 9, idx = task & 511;
                int r = idx >> 3, c8 = idx & 7;
                const uint4* src = (arr ? vl4 : vh4) + (size_t)(dc * 64 + r) * 128 + (mbase >> 3) + c8;
                cpa16(bo + (uint32_t)arr * 9216 + (uint32_t)(r * 72 + c8 * 8) * 2, src);
            }
        }
    }
    CP_COMMIT();
}

__global__ __launch_bounds__(256, 1) void attn_kernel(float* __restrict__ out)
{
    extern __shared__ char sm[];
    const uint32_t sb = smem_u32(sm);
    __half* QH = (__half*)(sm + A_QH);
    __half* QL = (__half*)(sm + A_QL);

    const int b = blockIdx.y, qbase = blockIdx.x * 128;
    const int tid = threadIdx.x, lane = tid & 31, w = tid >> 5;

    const uint32_t aQ = sb + A_QH + 2u * (uint32_t)(w * 16 * AT_QS) + aoff_b(lane, AT_QS);
    const uint32_t bKV = boff_b(lane, 72);

    const uint4* kh4 = (const uint4*)(g_k[0] + (size_t)b * SEQ * DIM);
    const uint4* kl4 = (const uint4*)(g_k[1] + (size_t)b * SEQ * DIM);
    const uint4* vh4 = (const uint4*)(g_vt[0] + (size_t)b * DIM * SEQ);
    const uint4* vl4 = (const uint4*)(g_vt[1] + (size_t)b * DIM * SEQ);

    issue_stage(sb, 0, tid, kh4, kl4, vh4, vl4);

    const uint4* qh4 = (const uint4*)(g_q[0] + (size_t)(b * SEQ + qbase) * DIM);
    const uint4* ql4 = (const uint4*)(g_q[1] + (size_t)(b * SEQ + qbase) * DIM);
#pragma unroll
    for (int it = 0; it < 32; it++) {
        int task = tid + 256 * it;               // 0..8191
        int arr = task >> 12, idx = task & 4095;
        int r = idx >> 5, c8 = idx & 31;
        uint4 v = (arr ? ql4 : qh4)[r * 32 + c8];
        *(uint4*)&((arr ? QL : QH)[r * AT_QS + c8 * 8]) = v;
    }

    float m0 = -1e30f, m1 = -1e30f, l0 = 0.f, l1 = 0.f;
    float o[32][4];
#pragma unroll
    for (int jn = 0; jn < 32; jn++)
#pragma unroll
        for (int c = 0; c < 4; c++) o[jn][c] = 0.f;

    int st = 0;
    for (int mt = 0; mt < 16; mt++) {
        float s[8][4];
#pragma unroll
        for (int nj = 0; nj < 8; nj++)
#pragma unroll
            for (int c = 0; c < 4; c++) s[nj][c] = 0.f;

        // ---- S = Q K^T: 4 K-chunk stages ----
        for (int dc = 0; dc < 4; dc++) {
            CP_WAIT0();
            __syncthreads();
            issue_stage(sb, st + 1, tid, kh4, kl4, vh4, vl4);
            const uint32_t kb = sb + A_BUF0 + (uint32_t)(st & 1) * BUFSZ;
#pragma unroll
            for (int ks = 0; ks < 4; ks++) {
                uint32_t ah[4], al[4];
                uint32_t ab = aQ + 2u * (uint32_t)(dc * 64 + ks * 16);
                ldm_a(ah, ab);
                ldm_a(al, ab + 67584);
#pragma unroll
                for (int nj = 0; nj < 8; nj++) {
                    uint32_t bh[2], bl[2];
                    uint32_t bb = kb + 2u * (uint32_t)(nj * 8 * 72 + ks * 16) + bKV;
                    ldm_b(bh, bb);
                    ldm_b(bl, bb + 9216);
                    mma16816(s[nj], ah, bh);
                    mma16816(s[nj], ah, bl);
                    mma16816(s[nj], al, bh);
                }
            }
            st++;
        }

        // ---- register-only online softmax; P -> fp16 (hi only) ----
        float mx0 = -1e30f, mx1 = -1e30f;
#pragma unroll
        for (int nj = 0; nj < 8; nj++) {
            mx0 = fmaxf(mx0, fmaxf(s[nj][0], s[nj][1]));
            mx1 = fmaxf(mx1, fmaxf(s[nj][2], s[nj][3]));
        }
        mx0 = fmaxf(mx0, __shfl_xor_sync(0xffffffffu, mx0, 1));
        mx0 = fmaxf(mx0, __shfl_xor_sync(0xffffffffu, mx0, 2));
        mx1 = fmaxf(mx1, __shfl_xor_sync(0xffffffffu, mx1, 1));
        mx1 = fmaxf(mx1, __shfl_xor_sync(0xffffffffu, mx1, 2));
        float mn0 = fmaxf(m0, mx0), mn1 = fmaxf(m1, mx1);
        float c0 = __expf(m0 - mn0), c1 = __expf(m1 - mn1);
        m0 = mn0; m1 = mn1;

        uint32_t ph[4][4];
        float sum0 = 0.f, sum1 = 0.f;
#pragma unroll
        for (int ks = 0; ks < 4; ks++) {
            float e00 = __expf(s[2*ks][0] - m0),   e01 = __expf(s[2*ks][1] - m0);
            float e02 = __expf(s[2*ks][2] - m1),   e03 = __expf(s[2*ks][3] - m1);
            float e10 = __expf(s[2*ks+1][0] - m0), e11 = __expf(s[2*ks+1][1] - m0);
            float e12 = __expf(s[2*ks+1][2] - m1), e13 = __expf(s[2*ks+1][3] - m1);
            sum0 += e00 + e01 + e10 + e11;
            sum1 += e02 + e03 + e12 + e13;
            ph[ks][0] = packh(__float2half_rn(e00), __float2half_rn(e01));
            ph[ks][1] = packh(__float2half_rn(e02), __float2half_rn(e03));
            ph[ks][2] = packh(__float2half_rn(e10), __float2half_rn(e11));
            ph[ks][3] = packh(__float2half_rn(e12), __float2half_rn(e13));
        }
        sum0 += __shfl_xor_sync(0xffffffffu, sum0, 1);
        sum0 += __shfl_xor_sync(0xffffffffu, sum0, 2);
        sum1 += __shfl_xor_sync(0xffffffffu, sum1, 1);
        sum1 += __shfl_xor_sync(0xffffffffu, sum1, 2);
        l0 = l0 * c0 + sum0;
        l1 = l1 * c1 + sum1;

#pragma unroll
        for (int jn = 0; jn < 32; jn++) {
            o[jn][0] *= c0; o[jn][1] *= c0;
            o[jn][2] *= c1; o[jn][3] *= c1;
        }

        // ---- O += P @ V: 4 V-chunk stages (P fp16 in registers, 2-MMA) ----
        for (int dc = 0; dc < 4; dc++) {
            CP_WAIT0();
            __syncthreads();
            issue_stage(sb, st + 1, tid, kh4, kl4, vh4, vl4);
            const uint32_t vb = sb + A_BUF0 + (uint32_t)(st & 1) * BUFSZ;
#pragma unroll
            for (int njl = 0; njl < 8; njl++) {
#pragma unroll
                for (int ks = 0; ks < 4; ks++) {
                    uint32_t bh[2], bl[2];
                    uint32_t bb = vb + 2u * (uint32_t)(njl * 8 * 72 + ks * 16) + bKV;
                    ldm_b(bh, bb);
                    ldm_b(bl, bb + 9216);
                    mma16816(o[dc * 8 + njl], ph[ks], bh);
                    mma16816(o[dc * 8 + njl], ph[ks], bl);
                }
            }
            st++;
        }
    }

    // ---- epilogue ----
    const float i0 = 1.0f / l0, i1 = 1.0f / l1;
    const int g0 = b * SEQ + qbase + w * 16 + (lane >> 2);
    const int g1 = g0 + 8;
#pragma unroll
    for (int jn = 0; jn < 32; jn++) {
        int d = jn * 8 + 2 * (lane & 3);
        *(float2*)&out[(size_t)g0 * DIM + d] = make_float2(o[jn][0] * i0, o[jn][1] * i0);
        *(float2*)&out[(size_t)g1 * DIM + d] = make_float2(o[jn][2] * i1, o[jn][3] * i1);
    }
}

// ---------------------------------------------------------------------------
extern "C" void kernel_launch(void* const* d_in, const int* in_sizes, int n_in,
                              void* d_out, int out_size)
{
    const float* traj = (const float*)d_in[0];
    const float* Wq = (const float*)d_in[1];
    const float* bq = (const float*)d_in[2];
    const float* Wk = (const float*)d_in[3];
    const float* bk = (const float*)d_in[4];
    const float* Wv = (const float*)d_in[5];
    const float* bv = (const float*)d_in[6];
    float* out = (float*)d_out;

    cudaFuncSetAttribute(proj_kernel, cudaFuncAttributeMaxDynamicSharedMemorySize, PJ_SMEM);
    cudaFuncSetAttribute(attn_kernel, cudaFuncAttributeMaxDynamicSharedMemorySize, AT_SMEM);

    split_x_kernel<<<8192, 256>>>(traj);
    split_w_kernel<<<192, 256>>>(Wq, Wk, Wv);
    proj_kernel<<<dim3(256, 2, 3), 256, PJ_SMEM>>>(bq, bk, bv);
    attn_kernel<<<dim3(8, 32), 256, AT_SMEM>>>(out);
}

// round 17
// speedup vs baseline: 4.2891x; 1.0201x over previous
#include <cuda_runtime.h>
#include <cuda_fp16.h>
#include <cstdint>

#define BATCH 32
#define SEQ   1024
#define DIM   256
#define NROWS (BATCH * SEQ)

// static scratch: fp16 hi/lo pairs
__device__ __align__(256) __half g_x [2][(size_t)NROWS * DIM];  // traj split
__device__ __align__(256) __half g_w [2][3][DIM * DIM];         // weights split
__device__ __align__(256) __half g_q [2][(size_t)NROWS * DIM];
__device__ __align__(256) __half g_k [2][(size_t)NROWS * DIM];
__device__ __align__(256) __half g_vt[2][(size_t)NROWS * DIM];  // [(b*256+d)*1024+m]

// ---------------- helpers ----------------
__device__ __forceinline__ uint32_t smem_u32(const void* p) {
    uint32_t a;
    asm("{ .reg .u64 t; cvta.to.shared.u64 t, %1; cvt.u32.u64 %0, t; }" : "=r"(a) : "l"(p));
    return a;
}
__device__ __forceinline__ void cpa16(uint32_t dst, const void* src) {
    asm volatile("cp.async.ca.shared.global [%0], [%1], 16;" :: "r"(dst), "l"(src));
}
#define CP_COMMIT() asm volatile("cp.async.commit_group;" ::: "memory")
#define CP_WAIT0()  asm volatile("cp.async.wait_group 0;" ::: "memory")

__device__ __forceinline__ void mma16816(float* d, const uint32_t* a, const uint32_t* b) {
    asm volatile("mma.sync.aligned.m16n8k16.row.col.f32.f16.f16.f32 "
        "{%0,%1,%2,%3}, {%4,%5,%6,%7}, {%8,%9}, {%0,%1,%2,%3};"
        : "+f"(d[0]), "+f"(d[1]), "+f"(d[2]), "+f"(d[3])
        : "r"(a[0]), "r"(a[1]), "r"(a[2]), "r"(a[3]), "r"(b[0]), "r"(b[1]));
}
__device__ __forceinline__ void ldm_a(uint32_t* a, uint32_t addr) {
    asm volatile("ldmatrix.sync.aligned.m8n8.x4.shared.b16 {%0,%1,%2,%3}, [%4];"
        : "=r"(a[0]), "=r"(a[1]), "=r"(a[2]), "=r"(a[3]) : "r"(addr));
}
// x4 B-load: fragments for TWO adjacent n-tiles (b[0],b[1] = nj; b[2],b[3] = nj+1)
__device__ __forceinline__ void ldm_b4(uint32_t* b, uint32_t addr) {
    asm volatile("ldmatrix.sync.aligned.m8n8.x4.shared.b16 {%0,%1,%2,%3}, [%4];"
        : "=r"(b[0]), "=r"(b[1]), "=r"(b[2]), "=r"(b[3]) : "r"(addr));
}
__device__ __forceinline__ uint32_t aoff_b(int lane, int S) {
    return 2u * (uint32_t)((lane < 16) ? lane * S : (lane - 16) * S + 8);
}
// per-thread byte offset for x4 B-load of a 16-row (two n-tile) block, stride S halfs
__device__ __forceinline__ uint32_t boff4_b(int lane, int S) {
    return 2u * (uint32_t)(((lane & 7) + ((lane >> 4) << 3)) * S + (((lane >> 3) & 1) << 3));
}
__device__ __forceinline__ void splitf(float x, __half& h, __half& l) {
    h = __float2half_rn(x);
    l = __float2half_rn(x - __half2float(h));
}
__device__ __forceinline__ uint32_t packh(__half a, __half b) {
    __half2 h2 = __halves2half2(a, b);
    return *reinterpret_cast<uint32_t*>(&h2);
}

// ---------------- split kernels ----------------
__global__ __launch_bounds__(256) void split_x_kernel(const float* __restrict__ X) {
    size_t i = ((size_t)blockIdx.x * 256 + threadIdx.x) * 4;
    float4 v = *(const float4*)(X + i);
    __half h0, l0, h1, l1, h2, l2, h3, l3;
    splitf(v.x, h0, l0); splitf(v.y, h1, l1); splitf(v.z, h2, l2); splitf(v.w, h3, l3);
    *(uint2*)&g_x[0][i] = make_uint2(packh(h0, h1), packh(h2, h3));
    *(uint2*)&g_x[1][i] = make_uint2(packh(l0, l1), packh(l2, l3));
}
__global__ __launch_bounds__(256) void split_w_kernel(
    const float* __restrict__ Wq, const float* __restrict__ Wk, const float* __restrict__ Wv) {
    size_t i = ((size_t)blockIdx.x * 256 + threadIdx.x) * 4;
    int z = (int)(i >> 16);
    size_t off = i & 65535;
    const float* W = (z == 0) ? Wq : ((z == 1) ? Wk : Wv);
    float4 v = *(const float4*)(W + off);
    __half h0, l0, h1, l1, h2, l2, h3, l3;
    splitf(v.x, h0, l0); splitf(v.y, h1, l1); splitf(v.z, h2, l2); splitf(v.w, h3, l3);
    *(uint2*)&g_w[0][z][off] = make_uint2(packh(h0, h1), packh(h2, h3));
    *(uint2*)&g_w[1][z][off] = make_uint2(packh(l0, l1), packh(l2, l3));
}

// ---------------- projection: Y = X @ W^T + b (fp16-split 3-MMA) ----------------
// z==2 (V) writes its output TRANSPOSED to g_vt via smem staging.
#define PJ_S 72
#define PJ_SMEM (4 * 18432)
__global__ __launch_bounds__(256, 2) void proj_kernel(
    const float* __restrict__ bq, const float* __restrict__ bk, const float* __restrict__ bv)
{
    extern __shared__ char sm[];
    __half* AH = (__half*)(sm);
    __half* AL = (__half*)(sm + 18432);
    __half* BH = (__half*)(sm + 36864);
    __half* BL = (__half*)(sm + 55296);

    const int tid = threadIdx.x, lane = tid & 31, w = tid >> 5;
    const int wy = w >> 1, wx = w & 1;
    const int rbase = blockIdx.x * 128, cbase = blockIdx.y * 128, z = blockIdx.z;
    const float* bias = (z == 0) ? bq : ((z == 1) ? bk : bv);

    const uint32_t sbp = smem_u32(sm);
    const uint32_t aoff = aoff_b(lane, PJ_S), boff4 = boff4_b(lane, PJ_S);

    const uint4* xh4 = (const uint4*)(g_x[0]);
    const uint4* xl4 = (const uint4*)(g_x[1]);
    const uint4* wh4 = (const uint4*)(g_w[0][z]);
    const uint4* wl4 = (const uint4*)(g_w[1][z]);

    float acc[2][8][4];
#pragma unroll
    for (int mi = 0; mi < 2; mi++)
#pragma unroll
        for (int nj = 0; nj < 8; nj++)
#pragma unroll
            for (int c = 0; c < 4; c++) acc[mi][nj][c] = 0.f;

    for (int kc = 0; kc < 4; kc++) {
        __syncthreads();
#pragma unroll
        for (int it = 0; it < 4; it++) {
            int task = tid + 256 * it;           // 0..1023
            int r = task >> 3, c8 = task & 7;
            uint4 va = xh4[(size_t)(rbase + r) * 32 + kc * 8 + c8];
            uint4 vb = xl4[(size_t)(rbase + r) * 32 + kc * 8 + c8];
            uint4 vc = wh4[(size_t)(cbase + r) * 32 + kc * 8 + c8];
            uint4 vd = wl4[(size_t)(cbase + r) * 32 + kc * 8 + c8];
            *(uint4*)&AH[r * PJ_S + c8 * 8] = va;
            *(uint4*)&AL[r * PJ_S + c8 * 8] = vb;
            *(uint4*)&BH[r * PJ_S + c8 * 8] = vc;
            *(uint4*)&BL[r * PJ_S + c8 * 8] = vd;
        }
        __syncthreads();
#pragma unroll
        for (int ks = 0; ks < 4; ks++) {
            uint32_t ah[2][4], al[2][4];
#pragma unroll
            for (int mi = 0; mi < 2; mi++) {
                uint32_t ab = sbp + 2u * (uint32_t)((wy * 32 + mi * 16) * PJ_S + ks * 16) + aoff;
                ldm_a(ah[mi], ab);
                ldm_a(al[mi], ab + 18432);
            }
#pragma unroll
            for (int njp = 0; njp < 4; njp++) {
                uint32_t bh4[4], bl4[4];
                uint32_t bb = sbp + 36864 + 2u * (uint32_t)((wx * 64 + njp * 16) * PJ_S + ks * 16) + boff4;
                ldm_b4(bh4, bb);
                ldm_b4(bl4, bb + 18432);
#pragma unroll
                for (int mi = 0; mi < 2; mi++) {
                    mma16816(acc[mi][2 * njp],     ah[mi], bh4);
                    mma16816(acc[mi][2 * njp],     ah[mi], bl4);
                    mma16816(acc[mi][2 * njp],     al[mi], bh4);
                    mma16816(acc[mi][2 * njp + 1], ah[mi], bh4 + 2);
                    mma16816(acc[mi][2 * njp + 1], ah[mi], bl4 + 2);
                    mma16816(acc[mi][2 * njp + 1], al[mi], bh4 + 2);
                }
            }
        }
    }

    if (z < 2) {
        uint32_t* dh = (uint32_t*)((z == 0) ? g_q[0] : g_k[0]);
        uint32_t* dl = (uint32_t*)((z == 0) ? g_q[1] : g_k[1]);
#pragma unroll
        for (int mi = 0; mi < 2; mi++) {
            int rA = rbase + wy * 32 + mi * 16 + (lane >> 2);
#pragma unroll
            for (int nj = 0; nj < 8; nj++) {
                int col = cbase + wx * 64 + nj * 8 + 2 * (lane & 3);
                float b0 = __ldg(&bias[col]), b1 = __ldg(&bias[col + 1]);
                __half h0, l0, h1, l1;
                float y0 = acc[mi][nj][0] + b0, y1 = acc[mi][nj][1] + b1;
                splitf(y0, h0, l0); splitf(y1, h1, l1);
                dh[(size_t)rA * 128 + (col >> 1)] = packh(h0, h1);
                dl[(size_t)rA * 128 + (col >> 1)] = packh(l0, l1);
                float y2 = acc[mi][nj][2] + b0, y3 = acc[mi][nj][3] + b1;
                splitf(y2, h0, l0); splitf(y3, h1, l1);
                dh[(size_t)(rA + 8) * 128 + (col >> 1)] = packh(h0, h1);
                dl[(size_t)(rA + 8) * 128 + (col >> 1)] = packh(l0, l1);
            }
        }
    } else {
        // V: stage transposed tile [d 128][m 136] then write g_vt coalesced
        __syncthreads();
        __half* SH = (__half*)sm;              // 128*136*2 = 34816 B
        __half* SL = (__half*)(sm + 34816);
#pragma unroll
        for (int mi = 0; mi < 2; mi++) {
            int rowl = wy * 32 + mi * 16 + (lane >> 2);
#pragma unroll
            for (int nj = 0; nj < 8; nj++) {
                int coll = wx * 64 + nj * 8 + 2 * (lane & 3);
                float b0 = __ldg(&bias[cbase + coll]), b1 = __ldg(&bias[cbase + coll + 1]);
                __half h, l;
                splitf(acc[mi][nj][0] + b0, h, l);
                SH[coll * 136 + rowl] = h; SL[coll * 136 + rowl] = l;
                splitf(acc[mi][nj][1] + b1, h, l);
                SH[(coll + 1) * 136 + rowl] = h; SL[(coll + 1) * 136 + rowl] = l;
                splitf(acc[mi][nj][2] + b0, h, l);
                SH[coll * 136 + rowl + 8] = h; SL[coll * 136 + rowl + 8] = l;
                splitf(acc[mi][nj][3] + b1, h, l);
                SH[(coll + 1) * 136 + rowl + 8] = h; SL[(coll + 1) * 136 + rowl + 8] = l;
            }
        }
        __syncthreads();
        const int batch = rbase >> 10, mb = rbase & 1023;
        uint4* vth = (uint4*)(g_vt[0]);
        uint4* vtl = (uint4*)(g_vt[1]);
#pragma unroll
        for (int it = 0; it < 16; it++) {
            int task = tid + 256 * it;           // 0..4095
            int arr = task >> 11, idx = task & 2047;
            int d = idx >> 4, c8 = idx & 15;
            uint4 v = *(uint4*)&((arr ? SL : SH)[d * 136 + c8 * 8]);
            (arr ? vtl : vth)[(size_t)(batch * 256 + cbase + d) * 128 + (mb >> 3) + c8] = v;
        }
    }
}

// ---------------- attention: register-softmax flash, 128 q-rows/CTA, kv-tile 64 ----------------
#define AT_QS 264
#define A_QH   0
#define A_QL   67584
#define A_BUF0 135168
#define BUFSZ  18432
#define AT_SMEM 172032

__device__ __forceinline__ void issue_stage(uint32_t sb, int st, int tid,
    const uint4* kh4, const uint4* kl4, const uint4* vh4, const uint4* vl4)
{
    if (st < 128) {
        int mt2 = st >> 3, ph2 = st & 7;
        uint32_t bo = sb + A_BUF0 + (uint32_t)(st & 1) * BUFSZ;
        int mbase = mt2 * 64;
        if (ph2 < 4) {
            int dc = ph2;                         // K: [m 64][64 d-chunk], stride 72
#pragma unroll
            for (int it = 0; it < 4; it++) {
                int task = tid + 256 * it;        // 0..1023
                int arr = task >> 9, idx = task & 511;
                int r = idx >> 3, c8 = idx & 7;
                const uint4* src = (arr ? kl4 : kh4) + (size_t)(mbase + r) * 32 + dc * 8 + c8;
                cpa16(bo + (uint32_t)arr * 9216 + (uint32_t)(r * 72 + c8 * 8) * 2, src);
            }
        } else {
            int dc = ph2 - 4;                     // V^T: [d 64][m 64], stride 72
#pragma unroll
            for (int it = 0; it < 4; it++) {
                int task = tid + 256 * it;
                int arr = task >> 9, idx = task & 511;
                int r = idx >> 3, c8 = idx & 7;
                const uint4* src = (arr ? vl4 : vh4) + (size_t)(dc * 64 + r) * 128 + (mbase >> 3) + c8;
                cpa16(bo + (uint32_t)arr * 9216 + (uint32_t)(r * 72 + c8 * 8) * 2, src);
            }
        }
    }
    CP_COMMIT();
}

__global__ __launch_bounds__(256, 1) void attn_kernel(float* __restrict__ out)
{
    extern __shared__ char sm[];
    const uint32_t sb = smem_u32(sm);
    __half* QH = (__half*)(sm + A_QH);
    __half* QL = (__half*)(sm + A_QL);

    const int b = blockIdx.y, qbase = blockIdx.x * 128;
    const int tid = threadIdx.x, lane = tid & 31, w = tid >> 5;

    const uint32_t aQ = sb + A_QH + 2u * (uint32_t)(w * 16 * AT_QS) + aoff_b(lane, AT_QS);
    const uint32_t bKV4 = boff4_b(lane, 72);

    const uint4* kh4 = (const uint4*)(g_k[0] + (size_t)b * SEQ * DIM);
    const uint4* kl4 = (const uint4*)(g_k[1] + (size_t)b * SEQ * DIM);
    const uint4* vh4 = (const uint4*)(g_vt[0] + (size_t)b * DIM * SEQ);
    const uint4* vl4 = (const uint4*)(g_vt[1] + (size_t)b * DIM * SEQ);

    issue_stage(sb, 0, tid, kh4, kl4, vh4, vl4);

    const uint4* qh4 = (const uint4*)(g_q[0] + (size_t)(b * SEQ + qbase) * DIM);
    const uint4* ql4 = (const uint4*)(g_q[1] + (size_t)(b * SEQ + qbase) * DIM);
#pragma unroll
    for (int it = 0; it < 32; it++) {
        int task = tid + 256 * it;               // 0..8191
        int arr = task >> 12, idx = task & 4095;
        int r = idx >> 5, c8 = idx & 31;
        uint4 v = (arr ? ql4 : qh4)[r * 32 + c8];
        *(uint4*)&((arr ? QL : QH)[r * AT_QS + c8 * 8]) = v;
    }

    float m0 = -1e30f, m1 = -1e30f, l0 = 0.f, l1 = 0.f;
    float o[32][4];
#pragma unroll
    for (int jn = 0; jn < 32; jn++)
#pragma unroll
        for (int c = 0; c < 4; c++) o[jn][c] = 0.f;

    int st = 0;
    for (int mt = 0; mt < 16; mt++) {
        float s[8][4];
#pragma unroll
        for (int nj = 0; nj < 8; nj++)
#pragma unroll
            for (int c = 0; c < 4; c++) s[nj][c] = 0.f;

        // ---- S = Q K^T: 4 K-chunk stages ----
        for (int dc = 0; dc < 4; dc++) {
            CP_WAIT0();
            __syncthreads();
            issue_stage(sb, st + 1, tid, kh4, kl4, vh4, vl4);
            const uint32_t kb = sb + A_BUF0 + (uint32_t)(st & 1) * BUFSZ;
#pragma unroll
            for (int ks = 0; ks < 4; ks++) {
                uint32_t ah[4], al[4];
                uint32_t ab = aQ + 2u * (uint32_t)(dc * 64 + ks * 16);
                ldm_a(ah, ab);
                ldm_a(al, ab + 67584);
#pragma unroll
                for (int njp = 0; njp < 4; njp++) {
                    uint32_t bh4[4], bl4[4];
                    uint32_t bb = kb + 2u * (uint32_t)(njp * 16 * 72 + ks * 16) + bKV4;
                    ldm_b4(bh4, bb);
                    ldm_b4(bl4, bb + 9216);
                    mma16816(s[2 * njp],     ah, bh4);
                    mma16816(s[2 * njp],     ah, bl4);
                    mma16816(s[2 * njp],     al, bh4);
                    mma16816(s[2 * njp + 1], ah, bh4 + 2);
                    mma16816(s[2 * njp + 1], ah, bl4 + 2);
                    mma16816(s[2 * njp + 1], al, bh4 + 2);
                }
            }
            st++;
        }

        // ---- register-only online softmax; P -> fp16 (hi only) ----
        float mx0 = -1e30f, mx1 = -1e30f;
#pragma unroll
        for (int nj = 0; nj < 8; nj++) {
            mx0 = fmaxf(mx0, fmaxf(s[nj][0], s[nj][1]));
            mx1 = fmaxf(mx1, fmaxf(s[nj][2], s[nj][3]));
        }
        mx0 = fmaxf(mx0, __shfl_xor_sync(0xffffffffu, mx0, 1));
        mx0 = fmaxf(mx0, __shfl_xor_sync(0xffffffffu, mx0, 2));
        mx1 = fmaxf(mx1, __shfl_xor_sync(0xffffffffu, mx1, 1));
        mx1 = fmaxf(mx1, __shfl_xor_sync(0xffffffffu, mx1, 2));
        float mn0 = fmaxf(m0, mx0), mn1 = fmaxf(m1, mx1);
        float c0 = __expf(m0 - mn0), c1 = __expf(m1 - mn1);
        m0 = mn0; m1 = mn1;

        uint32_t ph[4][4];
        float sum0 = 0.f, sum1 = 0.f;
#pragma unroll
        for (int ks = 0; ks < 4; ks++) {
            float e00 = __expf(s[2*ks][0] - m0),   e01 = __expf(s[2*ks][1] - m0);
            float e02 = __expf(s[2*ks][2] - m1),   e03 = __expf(s[2*ks][3] - m1);
            float e10 = __expf(s[2*ks+1][0] - m0), e11 = __expf(s[2*ks+1][1] - m0);
            float e12 = __expf(s[2*ks+1][2] - m1), e13 = __expf(s[2*ks+1][3] - m1);
            sum0 += e00 + e01 + e10 + e11;
            sum1 += e02 + e03 + e12 + e13;
            ph[ks][0] = packh(__float2half_rn(e00), __float2half_rn(e01));
            ph[ks][1] = packh(__float2half_rn(e02), __float2half_rn(e03));
            ph[ks][2] = packh(__float2half_rn(e10), __float2half_rn(e11));
            ph[ks][3] = packh(__float2half_rn(e12), __float2half_rn(e13));
        }
        sum0 += __shfl_xor_sync(0xffffffffu, sum0, 1);
        sum0 += __shfl_xor_sync(0xffffffffu, sum0, 2);
        sum1 += __shfl_xor_sync(0xffffffffu, sum1, 1);
        sum1 += __shfl_xor_sync(0xffffffffu, sum1, 2);
        l0 = l0 * c0 + sum0;
        l1 = l1 * c1 + sum1;

#pragma unroll
        for (int jn = 0; jn < 32; jn++) {
            o[jn][0] *= c0; o[jn][1] *= c0;
            o[jn][2] *= c1; o[jn][3] *= c1;
        }

        // ---- O += P @ V: 4 V-chunk stages (P fp16 in registers, 2-MMA) ----
        for (int dc = 0; dc < 4; dc++) {
            CP_WAIT0();
            __syncthreads();
            issue_stage(sb, st + 1, tid, kh4, kl4, vh4, vl4);
            const uint32_t vb = sb + A_BUF0 + (uint32_t)(st & 1) * BUFSZ;
#pragma unroll
            for (int njlp = 0; njlp < 4; njlp++) {
#pragma unroll
                for (int ks = 0; ks < 4; ks++) {
                    uint32_t bh4[4], bl4[4];
                    uint32_t bb = vb + 2u * (uint32_t)(njlp * 16 * 72 + ks * 16) + bKV4;
                    ldm_b4(bh4, bb);
                    ldm_b4(bl4, bb + 9216);
                    mma16816(o[dc * 8 + 2 * njlp],     ph[ks], bh4);
                    mma16816(o[dc * 8 + 2 * njlp],     ph[ks], bl4);
                    mma16816(o[dc * 8 + 2 * njlp + 1], ph[ks], bh4 + 2);
                    mma16816(o[dc * 8 + 2 * njlp + 1], ph[ks], bl4 + 2);
                }
            }
            st++;
        }
    }

    // ---- epilogue ----
    const float i0 = 1.0f / l0, i1 = 1.0f / l1;
    const int g0 = b * SEQ + qbase + w * 16 + (lane >> 2);
    const int g1 = g0 + 8;
#pragma unroll
    for (int jn = 0; jn < 32; jn++) {
        int d = jn * 8 + 2 * (lane & 3);
        *(float2*)&out[(size_t)g0 * DIM + d] = make_float2(o[jn][0] * i0, o[jn][1] * i0);
        *(float2*)&out[(size_t)g1 * DIM + d] = make_float2(o[jn][2] * i1, o[jn][3] * i1);
    }
}

// ---------------------------------------------------------------------------
extern "C" void kernel_launch(void* const* d_in, const int* in_sizes, int n_in,
                              void* d_out, int out_size)
{
    const float* traj = (const float*)d_in[0];
    const float* Wq = (const float*)d_in[1];
    const float* bq = (const float*)d_in[2];
    const float* Wk = (const float*)d_in[3];
    const float* bk = (const float*)d_in[4];
    const float* Wv = (const float*)d_in[5];
    const float* bv = (const float*)d_in[6];
    float* out = (float*)d_out;

    cudaFuncSetAttribute(proj_kernel, cudaFuncAttributeMaxDynamicSharedMemorySize, PJ_SMEM);
    cudaFuncSetAttribute(attn_kernel, cudaFuncAttributeMaxDynamicSharedMemorySize, AT_SMEM);

    split_x_kernel<<<8192, 256>>>(traj);
    split_w_kernel<<<192, 256>>>(Wq, Wk, Wv);
    proj_kernel<<<dim3(256, 2, 3), 256, PJ_SMEM>>>(bq, bk, bv);
    attn_kernel<<<dim3(8, 32), 256, AT_SMEM>>>(out);
}